// round 4
// baseline (speedup 1.0000x reference)
#include <cuda_runtime.h>
#include <cuda_bf16.h>

// Problem constants
#define NN      20000        // nodes
#define NE      320000       // raw edges
#define NET     340000       // edges + self loops
#define IN_CH   256
#define HID     128
#define HEADS   4
#define F1      (HEADS*HID)  // 512
#define NG      128          // graphs
#define OC      16
#define NEG     0.2f

// ------------------------- device scratch (no allocs allowed) -------------------------
__device__ float g_h1   [NN * F1];     // x @ W1
__device__ float g_h1b  [NN * F1];     // relu(agg1 + b1)
__device__ float g_h2   [NN * HID];    // h1b @ W2
__device__ float g_out2 [NN * HID];    // agg2 + b2
__device__ float g_as1  [NN * HEADS];
__device__ float g_ad1  [NN * HEADS];
__device__ float g_as2  [NN];
__device__ float g_ad2  [NN];
__device__ int   g_counts [NN];
__device__ int   g_rowstart[NN + 1];
__device__ int   g_cursor [NN];
__device__ int   g_csrsrc [NET];
__device__ float g_pooled [NG * HID];
__device__ float g_gcnt   [NG];
__device__ int   g_idx64;              // 1 if index inputs are int64, 0 if int32

// ------------------------- helpers -------------------------
__device__ __forceinline__ float warpMax(float v) {
    #pragma unroll
    for (int o = 16; o > 0; o >>= 1) v = fmaxf(v, __shfl_xor_sync(0xffffffffu, v, o));
    return v;
}
__device__ __forceinline__ float warpSum(float v) {
    #pragma unroll
    for (int o = 16; o > 0; o >>= 1) v += __shfl_xor_sync(0xffffffffu, v, o);
    return v;
}
__device__ __forceinline__ float lrelu(float x) { return x > 0.f ? x : NEG * x; }

__device__ __forceinline__ int clampi(int v, int hi) {  // clamp to [0, hi)
    return v < 0 ? 0 : (v >= hi ? hi - 1 : v);
}
__device__ __forceinline__ int idx_at(const void* p, int i) {
    if (g_idx64) return (int)((const long long*)p)[i];
    return ((const int*)p)[i];
}

// ------------------------- dtype detection -------------------------
// If edge_index is int64 (values < 2^31), every odd 32-bit word is 0.
// If int32, odd words are random node ids (all-zero over 64 samples ~ impossible).
__global__ void detect_kernel(const int* __restrict__ ei32) {
    int allzero = 1;
    #pragma unroll 1
    for (int i = 1; i < 128; i += 2)
        if (ei32[i] != 0) { allzero = 0; break; }
    g_idx64 = allzero;
}

// ------------------------- zero scratch -------------------------
__global__ void zero_kernel() {
    int i = blockIdx.x * blockDim.x + threadIdx.x;
    if (i < NN) g_counts[i] = 0;
    if (i < NG * HID) g_pooled[i] = 0.f;
    if (i < NG) g_gcnt[i] = 0.f;
}

// ------------------------- CSR build -------------------------
__global__ void hist_kernel(const void* __restrict__ ei) {
    int i = blockIdx.x * blockDim.x + threadIdx.x;
    if (i >= NET) return;
    int dst = (i < NE) ? clampi(idx_at(ei, NE + i), NN) : (i - NE);
    atomicAdd(&g_counts[dst], 1);
}

__global__ void scan_kernel() {
    __shared__ int sbuf[1024];
    __shared__ int run;
    int t = threadIdx.x;
    if (t == 0) { run = 0; g_rowstart[0] = 0; }
    __syncthreads();
    for (int base = 0; base < NN; base += 1024) {
        int v = (base + t < NN) ? g_counts[base + t] : 0;
        sbuf[t] = v;
        __syncthreads();
        #pragma unroll
        for (int off = 1; off < 1024; off <<= 1) {
            int x = (t >= off) ? sbuf[t - off] : 0;
            __syncthreads();
            sbuf[t] += x;
            __syncthreads();
        }
        int incl = sbuf[t];
        if (base + t < NN) {
            g_rowstart[base + t + 1] = run + incl;
            g_cursor[base + t]       = run + incl - v;   // exclusive prefix
        }
        __syncthreads();
        if (t == 0) run += sbuf[1023];
        __syncthreads();
    }
}

__global__ void scatter_kernel(const void* __restrict__ ei) {
    int i = blockIdx.x * blockDim.x + threadIdx.x;
    if (i >= NET) return;
    int src, dst;
    if (i < NE) {
        src = clampi(idx_at(ei, i), NN);
        dst = clampi(idx_at(ei, NE + i), NN);
    } else {
        src = dst = i - NE;
    }
    int pos = atomicAdd(&g_cursor[dst], 1);
    g_csrsrc[pos] = src;
}

// ------------------------- SGEMM core (64x64 tile, 4x4 per thread) -------------------------
// C[M,N] = A[M,K] @ B[K,N], row-major. N % 64 == 0, K % 16 == 0; only M guarded.
#define BM 64
#define BN 64
#define BK 16
__device__ __forceinline__ void sgemm_body(const float* __restrict__ A,
                                           const float* __restrict__ B,
                                           float* __restrict__ C,
                                           int M, int N, int K) {
    __shared__ float As[BK][BM];
    __shared__ float Bs[BK][BN];
    int tid = threadIdx.x;
    int tx = tid & 15;          // 0..15 (col group)
    int ty = tid >> 4;          // 0..15 (row group)
    int rowBase = blockIdx.y * BM;
    int colBase = blockIdx.x * BN;

    int aCol = tid & (BK - 1);  // 0..15
    int aRow0 = tid >> 4;       // 0..15
    int bCol = tid & (BN - 1);  // 0..63
    int bRow0 = tid >> 6;       // 0..3

    float acc[4][4] = {};

    for (int k0 = 0; k0 < K; k0 += BK) {
        #pragma unroll
        for (int i = 0; i < 4; i++) {
            int r = aRow0 + 16 * i;
            int gr = rowBase + r;
            As[aCol][r] = (gr < M) ? A[(long long)gr * K + k0 + aCol] : 0.f;
        }
        #pragma unroll
        for (int i = 0; i < 4; i++) {
            int r = bRow0 + 4 * i;
            Bs[r][bCol] = B[(long long)(k0 + r) * N + colBase + bCol];
        }
        __syncthreads();
        #pragma unroll
        for (int kk = 0; kk < BK; kk++) {
            float ra[4], rb[4];
            #pragma unroll
            for (int m = 0; m < 4; m++) ra[m] = As[kk][ty * 4 + m];
            #pragma unroll
            for (int n = 0; n < 4; n++) rb[n] = Bs[kk][tx * 4 + n];
            #pragma unroll
            for (int m = 0; m < 4; m++)
                #pragma unroll
                for (int n = 0; n < 4; n++) acc[m][n] += ra[m] * rb[n];
        }
        __syncthreads();
    }
    #pragma unroll
    for (int m = 0; m < 4; m++) {
        int gr = rowBase + ty * 4 + m;
        if (gr >= M) continue;
        #pragma unroll
        for (int n = 0; n < 4; n++)
            C[(long long)gr * N + colBase + tx * 4 + n] = acc[m][n];
    }
}

// gemm1: g_h1 = x @ W1   (M=NN, N=F1, K=IN_CH)
__global__ __launch_bounds__(256) void gemm1_kernel(const float* __restrict__ x,
                                                    const float* __restrict__ W1) {
    sgemm_body(x, W1, g_h1, NN, F1, IN_CH);
}

// gemm2: g_h2 = g_h1b @ W2   (M=NN, N=HID, K=F1)
__global__ __launch_bounds__(256) void gemm2_kernel(const float* __restrict__ W2) {
    sgemm_body(g_h1b, W2, g_h2, NN, HID, F1);
}

// ------------------------- attention coefficients -------------------------
// Layer 1: a_src[n,h] = dot(h1[n,h,:], as1[h,:]); same for a_dst. block=128, grid=NN
__global__ void att1_kernel(const float* __restrict__ as1, const float* __restrict__ ad1) {
    int n = blockIdx.x, t = threadIdx.x;
    int warp = t >> 5, lane = t & 31;
    float vs[HEADS], vd[HEADS];
    #pragma unroll
    for (int h = 0; h < HEADS; h++) {
        float x = g_h1[(long long)n * F1 + h * HID + t];
        vs[h] = x * as1[h * HID + t];
        vd[h] = x * ad1[h * HID + t];
    }
    __shared__ float ss[4][HEADS], sd[4][HEADS];
    #pragma unroll
    for (int h = 0; h < HEADS; h++) { vs[h] = warpSum(vs[h]); vd[h] = warpSum(vd[h]); }
    if (lane == 0) {
        #pragma unroll
        for (int h = 0; h < HEADS; h++) { ss[warp][h] = vs[h]; sd[warp][h] = vd[h]; }
    }
    __syncthreads();
    if (t < HEADS) {
        float a = ss[0][t] + ss[1][t] + ss[2][t] + ss[3][t];
        float b = sd[0][t] + sd[1][t] + sd[2][t] + sd[3][t];
        g_as1[n * HEADS + t] = a;
        g_ad1[n * HEADS + t] = b;
    }
}

// Layer 2 (1 head)
__global__ void att2_kernel(const float* __restrict__ as2, const float* __restrict__ ad2) {
    int n = blockIdx.x, t = threadIdx.x;
    int warp = t >> 5, lane = t & 31;
    float x = g_h2[(long long)n * HID + t];
    float vs = x * as2[t], vd = x * ad2[t];
    __shared__ float ss[4], sd[4];
    vs = warpSum(vs); vd = warpSum(vd);
    if (lane == 0) { ss[warp] = vs; sd[warp] = vd; }
    __syncthreads();
    if (t == 0) {
        g_as2[n] = ss[0] + ss[1] + ss[2] + ss[3];
        g_ad2[n] = sd[0] + sd[1] + sd[2] + sd[3];
    }
}

// ------------------------- layer-1 aggregation (softmax + gather), block per node ------
__global__ __launch_bounds__(128) void agg1_kernel(const float* __restrict__ b1) {
    int n = blockIdx.x, t = threadIdx.x;
    int warp = t >> 5, lane = t & 31;
    int beg = g_rowstart[n], end = g_rowstart[n + 1];

    __shared__ float s_adst[HEADS];
    if (t < HEADS) s_adst[t] = g_ad1[n * HEADS + t];
    __syncthreads();

    // pass 1: max per head
    float m[HEADS] = {-1e30f, -1e30f, -1e30f, -1e30f};
    for (int j = beg + t; j < end; j += 128) {
        int s = g_csrsrc[j];
        #pragma unroll
        for (int h = 0; h < HEADS; h++) {
            float e = lrelu(g_as1[s * HEADS + h] + s_adst[h]);
            m[h] = fmaxf(m[h], e);
        }
    }
    __shared__ float wr[4][HEADS];
    #pragma unroll
    for (int h = 0; h < HEADS; h++) m[h] = warpMax(m[h]);
    if (lane == 0) {
        #pragma unroll
        for (int h = 0; h < HEADS; h++) wr[warp][h] = m[h];
    }
    __syncthreads();
    __shared__ float fmx[HEADS];
    if (t < HEADS) fmx[t] = fmaxf(fmaxf(wr[0][t], wr[1][t]), fmaxf(wr[2][t], wr[3][t]));
    __syncthreads();

    // pass 2: sum of exp
    float ssum[HEADS] = {0, 0, 0, 0};
    for (int j = beg + t; j < end; j += 128) {
        int s = g_csrsrc[j];
        #pragma unroll
        for (int h = 0; h < HEADS; h++) {
            float e = lrelu(g_as1[s * HEADS + h] + s_adst[h]);
            ssum[h] += __expf(e - fmx[h]);
        }
    }
    #pragma unroll
    for (int h = 0; h < HEADS; h++) ssum[h] = warpSum(ssum[h]);
    if (lane == 0) {
        #pragma unroll
        for (int h = 0; h < HEADS; h++) wr[warp][h] = ssum[h];
    }
    __syncthreads();
    __shared__ float finv[HEADS];
    if (t < HEADS) finv[t] = 1.f / (wr[0][t] + wr[1][t] + wr[2][t] + wr[3][t]);
    __syncthreads();

    // pass 3: weighted gather, chunks of 32 edges
    __shared__ float w[32 * HEADS];
    __shared__ int ssrc[32];
    float acc[HEADS] = {0, 0, 0, 0};
    for (int base = beg; base < end; base += 32) {
        int cnt = min(32, end - base);
        int je = t >> 2, h = t & 3;
        if (je < cnt) {
            int s = g_csrsrc[base + je];
            if (h == 0) ssrc[je] = s;
            float e = lrelu(g_as1[s * HEADS + h] + s_adst[h]);
            w[je * HEADS + h] = __expf(e - fmx[h]) * finv[h];
        }
        __syncthreads();
        for (int q = 0; q < cnt; q++) {
            int s = ssrc[q];
            const float* hp = &g_h1[(long long)s * F1];
            #pragma unroll
            for (int hh = 0; hh < HEADS; hh++)
                acc[hh] += w[q * HEADS + hh] * hp[hh * HID + t];
        }
        __syncthreads();
    }
    #pragma unroll
    for (int h = 0; h < HEADS; h++) {
        float v = acc[h] + b1[h * HID + t];
        g_h1b[(long long)n * F1 + h * HID + t] = v > 0.f ? v : 0.f;   // relu fused
    }
}

// ------------------------- layer-2 aggregation (1 head) -------------------------
__global__ __launch_bounds__(128) void agg2_kernel(const float* __restrict__ b2) {
    int n = blockIdx.x, t = threadIdx.x;
    int warp = t >> 5, lane = t & 31;
    int beg = g_rowstart[n], end = g_rowstart[n + 1];
    float adst = g_ad2[n];

    float m = -1e30f;
    for (int j = beg + t; j < end; j += 128)
        m = fmaxf(m, lrelu(g_as2[g_csrsrc[j]] + adst));
    __shared__ float wr[4];
    m = warpMax(m);
    if (lane == 0) wr[warp] = m;
    __syncthreads();
    __shared__ float fmx, finv;
    if (t == 0) fmx = fmaxf(fmaxf(wr[0], wr[1]), fmaxf(wr[2], wr[3]));
    __syncthreads();

    float s = 0.f;
    for (int j = beg + t; j < end; j += 128)
        s += __expf(lrelu(g_as2[g_csrsrc[j]] + adst) - fmx);
    s = warpSum(s);
    if (lane == 0) wr[warp] = s;
    __syncthreads();
    if (t == 0) finv = 1.f / (wr[0] + wr[1] + wr[2] + wr[3]);
    __syncthreads();

    __shared__ float w[128];
    __shared__ int ssrc[128];
    float acc = 0.f;
    for (int base = beg; base < end; base += 128) {
        int cnt = min(128, end - base);
        if (t < cnt) {
            int sidx = g_csrsrc[base + t];
            ssrc[t] = sidx;
            w[t] = __expf(lrelu(g_as2[sidx] + adst) - fmx) * finv;
        }
        __syncthreads();
        for (int q = 0; q < cnt; q++)
            acc += w[q] * g_h2[(long long)ssrc[q] * HID + t];
        __syncthreads();
    }
    g_out2[(long long)n * HID + t] = acc + b2[t];
}

// ------------------------- global mean pool -------------------------
__global__ void pool_kernel(const void* __restrict__ batch) {
    int n = blockIdx.x, t = threadIdx.x;
    int g = clampi(idx_at(batch, n), NG);
    atomicAdd(&g_pooled[g * HID + t], g_out2[(long long)n * HID + t]);
    if (t == 0) atomicAdd(&g_gcnt[g], 1.0f);
}

// ------------------------- MLP head -------------------------
__global__ void mlp_kernel(const float* __restrict__ Wm1, const float* __restrict__ bm1,
                           const float* __restrict__ Wm2, const float* __restrict__ bm2,
                           float* __restrict__ out) {
    int g = blockIdx.x, t = threadIdx.x;
    __shared__ float p[HID], z[HID];
    float c = fmaxf(g_gcnt[g], 1.0f);
    p[t] = g_pooled[g * HID + t] / c;
    __syncthreads();
    float a = bm1[t];
    #pragma unroll 8
    for (int k = 0; k < HID; k++) a += p[k] * Wm1[k * HID + t];
    z[t] = a > 0.f ? a : 0.f;
    __syncthreads();
    if (t < OC) {
        float o = bm2[t];
        #pragma unroll 8
        for (int k = 0; k < HID; k++) o += z[k] * Wm2[k * OC + t];
        out[g * OC + t] = o;
    }
}

// ------------------------- launch -------------------------
extern "C" void kernel_launch(void* const* d_in, const int* in_sizes, int n_in,
                              void* d_out, int out_size) {
    const float* x    = (const float*)d_in[0];
    const void*  ei   = d_in[1];
    const void*  bat  = d_in[2];
    const float* W1   = (const float*)d_in[3];
    const float* as1  = (const float*)d_in[4];
    const float* ad1  = (const float*)d_in[5];
    const float* b1   = (const float*)d_in[6];
    const float* W2   = (const float*)d_in[7];
    const float* as2  = (const float*)d_in[8];
    const float* ad2  = (const float*)d_in[9];
    const float* b2   = (const float*)d_in[10];
    const float* Wm1  = (const float*)d_in[11];
    const float* bm1  = (const float*)d_in[12];
    const float* Wm2  = (const float*)d_in[13];
    const float* bm2  = (const float*)d_in[14];
    float* out = (float*)d_out;

    // dtype detection + CSR build
    detect_kernel<<<1, 1>>>((const int*)ei);
    zero_kernel<<<(NN + 255) / 256, 256>>>();
    hist_kernel<<<(NET + 255) / 256, 256>>>(ei);
    scan_kernel<<<1, 1024>>>();
    scatter_kernel<<<(NET + 255) / 256, 256>>>(ei);

    // Layer 1
    {
        dim3 grid(F1 / BN, (NN + BM - 1) / BM);
        gemm1_kernel<<<grid, 256>>>(x, W1);
    }
    att1_kernel<<<NN, 128>>>(as1, ad1);
    agg1_kernel<<<NN, 128>>>(b1);

    // Layer 2
    {
        dim3 grid(HID / BN, (NN + BM - 1) / BM);
        gemm2_kernel<<<grid, 256>>>(W2);
    }
    att2_kernel<<<NN, 128>>>(as2, ad2);
    agg2_kernel<<<NN, 128>>>(b2);

    // Pool + MLP
    pool_kernel<<<NN, HID>>>(bat);
    mlp_kernel<<<NG, HID>>>(Wm1, bm1, Wm2, bm2, out);
}

// round 5
// speedup vs baseline: 1.9517x; 1.9517x over previous
#include <cuda_runtime.h>
#include <cuda_bf16.h>

// Problem constants
#define NN      20000        // nodes
#define NE      320000       // raw edges
#define NET     340000       // edges + self loops
#define IN_CH   256
#define HID     128
#define HEADS   4
#define F1      (HEADS*HID)  // 512
#define NG      128          // graphs
#define OC      16
#define NEG     0.2f

// ------------------------- device scratch (no allocs allowed) -------------------------
__device__ float g_h1   [NN * F1];     // x @ W1
__device__ float g_h1b  [NN * F1];     // relu(agg1 + b1)
__device__ float g_h2   [NN * HID];    // h1b @ W2
__device__ float g_out2 [NN * HID];    // agg2 + b2
__device__ float g_as1  [NN * HEADS];
__device__ float g_ad1  [NN * HEADS];
__device__ float g_as2  [NN];
__device__ float g_ad2  [NN];
__device__ int   g_counts [NN];
__device__ int   g_rowstart[NN + 1];
__device__ int   g_cursor [NN];
__device__ int   g_csrsrc [NET];
__device__ float g_pooled [NG * HID];
__device__ float g_gcnt   [NG];
__device__ int   g_idx64;              // 1 if index inputs are int64, 0 if int32

#define SCH 1024
#define SNB ((NN + SCH - 1) / SCH)     // 20
__device__ int g_bsum[SNB];
__device__ int g_boff[SNB];

// ------------------------- helpers -------------------------
__device__ __forceinline__ float warpMax(float v) {
    #pragma unroll
    for (int o = 16; o > 0; o >>= 1) v = fmaxf(v, __shfl_xor_sync(0xffffffffu, v, o));
    return v;
}
__device__ __forceinline__ float warpSum(float v) {
    #pragma unroll
    for (int o = 16; o > 0; o >>= 1) v += __shfl_xor_sync(0xffffffffu, v, o);
    return v;
}
__device__ __forceinline__ float lrelu(float x) { return x > 0.f ? x : NEG * x; }

__device__ __forceinline__ int clampi(int v, int hi) {  // clamp to [0, hi)
    return v < 0 ? 0 : (v >= hi ? hi - 1 : v);
}
__device__ __forceinline__ int idx_at(const void* p, int i) {
    if (g_idx64) return (int)((const long long*)p)[i];
    return ((const int*)p)[i];
}

__device__ __forceinline__ unsigned f2tf32(float f) {
    unsigned r;
    asm("cvt.rna.tf32.f32 %0, %1;" : "=r"(r) : "f"(f));
    return r;
}
__device__ __forceinline__ void mma_tf32(float* c, unsigned a0, unsigned a1,
                                         unsigned a2, unsigned a3,
                                         unsigned b0, unsigned b1) {
    asm("mma.sync.aligned.m16n8k8.row.col.f32.tf32.tf32.f32 "
        "{%0,%1,%2,%3}, {%4,%5,%6,%7}, {%8,%9}, {%0,%1,%2,%3};"
        : "+f"(c[0]), "+f"(c[1]), "+f"(c[2]), "+f"(c[3])
        : "r"(a0), "r"(a1), "r"(a2), "r"(a3), "r"(b0), "r"(b1));
}

// ------------------------- dtype detection -------------------------
__global__ void detect_kernel(const int* __restrict__ ei32) {
    int allzero = 1;
    #pragma unroll 1
    for (int i = 1; i < 128; i += 2)
        if (ei32[i] != 0) { allzero = 0; break; }
    g_idx64 = allzero;
}

// ------------------------- zero scratch -------------------------
__global__ void zero_kernel() {
    int i = blockIdx.x * blockDim.x + threadIdx.x;
    if (i < NN) g_counts[i] = 0;
    if (i < NG * HID) g_pooled[i] = 0.f;
    if (i < NG) g_gcnt[i] = 0.f;
}

// ------------------------- CSR build -------------------------
__global__ void hist_kernel(const void* __restrict__ ei) {
    int i = blockIdx.x * blockDim.x + threadIdx.x;
    if (i >= NET) return;
    int dst = (i < NE) ? clampi(idx_at(ei, NE + i), NN) : (i - NE);
    atomicAdd(&g_counts[dst], 1);
}

// multi-block scan: phase 1 — per-block inclusive scan + block sums
__global__ void scan1_kernel() {
    __shared__ int sbuf[SCH];
    int b = blockIdx.x, t = threadIdx.x;
    int i = b * SCH + t;
    int v = (i < NN) ? g_counts[i] : 0;
    sbuf[t] = v;
    __syncthreads();
    #pragma unroll
    for (int off = 1; off < SCH; off <<= 1) {
        int x = (t >= off) ? sbuf[t - off] : 0;
        __syncthreads();
        sbuf[t] += x;
        __syncthreads();
    }
    if (i < NN) g_rowstart[i + 1] = sbuf[t];   // local inclusive, offset added later
    if (t == SCH - 1) g_bsum[b] = sbuf[t];
}

// phase 2 — scan block sums (tiny)
__global__ void scan2_kernel() {
    if (threadIdx.x == 0) {
        int run = 0;
        g_rowstart[0] = 0;
        #pragma unroll
        for (int b = 0; b < SNB; b++) { g_boff[b] = run; run += g_bsum[b]; }
    }
}

// phase 3 — add offsets, derive cursor
__global__ void scan3_kernel() {
    int i = blockIdx.x * blockDim.x + threadIdx.x;
    if (i >= NN) return;
    int fin = g_rowstart[i + 1] + g_boff[i >> 10];
    g_rowstart[i + 1] = fin;
    g_cursor[i] = fin - g_counts[i];
}

__global__ void scatter_kernel(const void* __restrict__ ei) {
    int i = blockIdx.x * blockDim.x + threadIdx.x;
    if (i >= NET) return;
    int src, dst;
    if (i < NE) {
        src = clampi(idx_at(ei, i), NN);
        dst = clampi(idx_at(ei, NE + i), NN);
    } else {
        src = dst = i - NE;
    }
    int pos = atomicAdd(&g_cursor[dst], 1);
    g_csrsrc[pos] = src;
}

// ------------------------- TF32 tensor-core GEMM -------------------------
// C[M,N] = A[M,K] @ B[K,N], row-major. N % 64 == 0, K % 32 == 0, only M guarded.
// Block tile 128x64, 8 warps as 4(M) x 2(N), warp tile 32x32, mma m16n8k8.
#define GBM 128
#define GBN 64
#define GBK 32
#define APAD 4   // As row stride 36 -> conflict-free fragment loads
#define BPAD 8   // Bs row stride 72 -> conflict-free fragment loads

__device__ __forceinline__ void tf32_gemm_body(const float* __restrict__ A,
                                               const float* __restrict__ B,
                                               float* __restrict__ C,
                                               int M, int N, int K) {
    __shared__ float As[GBM][GBK + APAD];
    __shared__ float Bs[GBK][GBN + BPAD];

    int tid  = threadIdx.x;
    int lane = tid & 31;
    int warp = tid >> 5;
    int wm = warp & 3;          // 0..3 -> M offset wm*32
    int wn = warp >> 2;         // 0..1 -> N offset wn*32
    int rowBase = blockIdx.y * GBM;
    int colBase = blockIdx.x * GBN;

    int q  = lane & 3;          // quad col
    int r0 = lane >> 2;         // quad row

    float acc[2][4][4] = {};

    // load indices
    int aRow = tid >> 3;            // 0..31
    int aCol = (tid & 7) * 4;       // 0,4,..,28
    int bRow = tid >> 4;            // 0..15
    int bCol = (tid & 15) * 4;      // 0..60

    for (int k0 = 0; k0 < K; k0 += GBK) {
        // A: 128x32, four passes of 32 rows, float4 each
        #pragma unroll
        for (int i = 0; i < 4; i++) {
            int row = aRow + 32 * i;
            int gr = rowBase + row;
            float4 v = make_float4(0.f, 0.f, 0.f, 0.f);
            if (gr < M) v = *(const float4*)&A[(long long)gr * K + k0 + aCol];
            *(float4*)&As[row][aCol] = v;
        }
        // B: 32x64, two passes of 16 rows
        #pragma unroll
        for (int i = 0; i < 2; i++) {
            int row = bRow + 16 * i;
            float4 v = *(const float4*)&B[(long long)(k0 + row) * N + colBase + bCol];
            *(float4*)&Bs[row][bCol] = v;
        }
        __syncthreads();

        #pragma unroll
        for (int kk = 0; kk < 4; kk++) {
            int kb = kk * 8;
            unsigned a[2][4], b[4][2];
            #pragma unroll
            for (int mf = 0; mf < 2; mf++) {
                int mrow = wm * 32 + mf * 16 + r0;
                a[mf][0] = f2tf32(As[mrow    ][kb + q    ]);
                a[mf][1] = f2tf32(As[mrow + 8][kb + q    ]);
                a[mf][2] = f2tf32(As[mrow    ][kb + q + 4]);
                a[mf][3] = f2tf32(As[mrow + 8][kb + q + 4]);
            }
            #pragma unroll
            for (int nf = 0; nf < 4; nf++) {
                int ncol = wn * 32 + nf * 8 + r0;
                b[nf][0] = f2tf32(Bs[kb + q    ][ncol]);
                b[nf][1] = f2tf32(Bs[kb + q + 4][ncol]);
            }
            #pragma unroll
            for (int mf = 0; mf < 2; mf++)
                #pragma unroll
                for (int nf = 0; nf < 4; nf++)
                    mma_tf32(acc[mf][nf], a[mf][0], a[mf][1], a[mf][2], a[mf][3],
                             b[nf][0], b[nf][1]);
        }
        __syncthreads();
    }

    // epilogue
    #pragma unroll
    for (int mf = 0; mf < 2; mf++) {
        int gr0 = rowBase + wm * 32 + mf * 16 + r0;
        #pragma unroll
        for (int nf = 0; nf < 4; nf++) {
            int gc = colBase + wn * 32 + nf * 8 + 2 * q;
            if (gr0 < M)
                *(float2*)&C[(long long)gr0 * N + gc] =
                    make_float2(acc[mf][nf][0], acc[mf][nf][1]);
            if (gr0 + 8 < M)
                *(float2*)&C[(long long)(gr0 + 8) * N + gc] =
                    make_float2(acc[mf][nf][2], acc[mf][nf][3]);
        }
    }
}

// gemm1: g_h1 = x @ W1   (M=NN, N=F1, K=IN_CH)
__global__ __launch_bounds__(256) void gemm1_kernel(const float* __restrict__ x,
                                                    const float* __restrict__ W1) {
    tf32_gemm_body(x, W1, g_h1, NN, F1, IN_CH);
}

// gemm2: g_h2 = g_h1b @ W2   (M=NN, N=HID, K=F1)
__global__ __launch_bounds__(256) void gemm2_kernel(const float* __restrict__ W2) {
    tf32_gemm_body(g_h1b, W2, g_h2, NN, HID, F1);
}

// ------------------------- attention coefficients -------------------------
__global__ void att1_kernel(const float* __restrict__ as1, const float* __restrict__ ad1) {
    int n = blockIdx.x, t = threadIdx.x;
    int warp = t >> 5, lane = t & 31;
    float vs[HEADS], vd[HEADS];
    #pragma unroll
    for (int h = 0; h < HEADS; h++) {
        float x = g_h1[(long long)n * F1 + h * HID + t];
        vs[h] = x * as1[h * HID + t];
        vd[h] = x * ad1[h * HID + t];
    }
    __shared__ float ss[4][HEADS], sd[4][HEADS];
    #pragma unroll
    for (int h = 0; h < HEADS; h++) { vs[h] = warpSum(vs[h]); vd[h] = warpSum(vd[h]); }
    if (lane == 0) {
        #pragma unroll
        for (int h = 0; h < HEADS; h++) { ss[warp][h] = vs[h]; sd[warp][h] = vd[h]; }
    }
    __syncthreads();
    if (t < HEADS) {
        g_as1[n * HEADS + t] = ss[0][t] + ss[1][t] + ss[2][t] + ss[3][t];
        g_ad1[n * HEADS + t] = sd[0][t] + sd[1][t] + sd[2][t] + sd[3][t];
    }
}

__global__ void att2_kernel(const float* __restrict__ as2, const float* __restrict__ ad2) {
    int n = blockIdx.x, t = threadIdx.x;
    int warp = t >> 5, lane = t & 31;
    float x = g_h2[(long long)n * HID + t];
    float vs = x * as2[t], vd = x * ad2[t];
    __shared__ float ss[4], sd[4];
    vs = warpSum(vs); vd = warpSum(vd);
    if (lane == 0) { ss[warp] = vs; sd[warp] = vd; }
    __syncthreads();
    if (t == 0) {
        g_as2[n] = ss[0] + ss[1] + ss[2] + ss[3];
        g_ad2[n] = sd[0] + sd[1] + sd[2] + sd[3];
    }
}

// ------------------------- layer-1 aggregation -------------------------
__global__ __launch_bounds__(128) void agg1_kernel(const float* __restrict__ b1) {
    int n = blockIdx.x, t = threadIdx.x;
    int warp = t >> 5, lane = t & 31;
    int beg = g_rowstart[n], end = g_rowstart[n + 1];

    __shared__ float s_adst[HEADS];
    if (t < HEADS) s_adst[t] = g_ad1[n * HEADS + t];
    __syncthreads();

    float m[HEADS] = {-1e30f, -1e30f, -1e30f, -1e30f};
    for (int j = beg + t; j < end; j += 128) {
        int s = g_csrsrc[j];
        #pragma unroll
        for (int h = 0; h < HEADS; h++) {
            float e = lrelu(g_as1[s * HEADS + h] + s_adst[h]);
            m[h] = fmaxf(m[h], e);
        }
    }
    __shared__ float wr[4][HEADS];
    #pragma unroll
    for (int h = 0; h < HEADS; h++) m[h] = warpMax(m[h]);
    if (lane == 0) {
        #pragma unroll
        for (int h = 0; h < HEADS; h++) wr[warp][h] = m[h];
    }
    __syncthreads();
    __shared__ float fmx[HEADS];
    if (t < HEADS) fmx[t] = fmaxf(fmaxf(wr[0][t], wr[1][t]), fmaxf(wr[2][t], wr[3][t]));
    __syncthreads();

    float ssum[HEADS] = {0, 0, 0, 0};
    for (int j = beg + t; j < end; j += 128) {
        int s = g_csrsrc[j];
        #pragma unroll
        for (int h = 0; h < HEADS; h++) {
            float e = lrelu(g_as1[s * HEADS + h] + s_adst[h]);
            ssum[h] += __expf(e - fmx[h]);
        }
    }
    #pragma unroll
    for (int h = 0; h < HEADS; h++) ssum[h] = warpSum(ssum[h]);
    if (lane == 0) {
        #pragma unroll
        for (int h = 0; h < HEADS; h++) wr[warp][h] = ssum[h];
    }
    __syncthreads();
    __shared__ float finv[HEADS];
    if (t < HEADS) finv[t] = 1.f / (wr[0][t] + wr[1][t] + wr[2][t] + wr[3][t]);
    __syncthreads();

    __shared__ float w[32 * HEADS];
    __shared__ int ssrc[32];
    float acc[HEADS] = {0, 0, 0, 0};
    for (int base = beg; base < end; base += 32) {
        int cnt = min(32, end - base);
        int je = t >> 2, h = t & 3;
        if (je < cnt) {
            int s = g_csrsrc[base + je];
            if (h == 0) ssrc[je] = s;
            float e = lrelu(g_as1[s * HEADS + h] + s_adst[h]);
            w[je * HEADS + h] = __expf(e - fmx[h]) * finv[h];
        }
        __syncthreads();
        for (int q = 0; q < cnt; q++) {
            int s = ssrc[q];
            const float* hp = &g_h1[(long long)s * F1];
            #pragma unroll
            for (int hh = 0; hh < HEADS; hh++)
                acc[hh] += w[q * HEADS + hh] * hp[hh * HID + t];
        }
        __syncthreads();
    }
    #pragma unroll
    for (int h = 0; h < HEADS; h++) {
        float v = acc[h] + b1[h * HID + t];
        g_h1b[(long long)n * F1 + h * HID + t] = v > 0.f ? v : 0.f;
    }
}

// ------------------------- layer-2 aggregation -------------------------
__global__ __launch_bounds__(128) void agg2_kernel(const float* __restrict__ b2) {
    int n = blockIdx.x, t = threadIdx.x;
    int warp = t >> 5, lane = t & 31;
    int beg = g_rowstart[n], end = g_rowstart[n + 1];
    float adst = g_ad2[n];

    float m = -1e30f;
    for (int j = beg + t; j < end; j += 128)
        m = fmaxf(m, lrelu(g_as2[g_csrsrc[j]] + adst));
    __shared__ float wr[4];
    m = warpMax(m);
    if (lane == 0) wr[warp] = m;
    __syncthreads();
    __shared__ float fmx, finv;
    if (t == 0) fmx = fmaxf(fmaxf(wr[0], wr[1]), fmaxf(wr[2], wr[3]));
    __syncthreads();

    float s = 0.f;
    for (int j = beg + t; j < end; j += 128)
        s += __expf(lrelu(g_as2[g_csrsrc[j]] + adst) - fmx);
    s = warpSum(s);
    if (lane == 0) wr[warp] = s;
    __syncthreads();
    if (t == 0) finv = 1.f / (wr[0] + wr[1] + wr[2] + wr[3]);
    __syncthreads();

    __shared__ float w[128];
    __shared__ int ssrc[128];
    float acc = 0.f;
    for (int base = beg; base < end; base += 128) {
        int cnt = min(128, end - base);
        if (t < cnt) {
            int sidx = g_csrsrc[base + t];
            ssrc[t] = sidx;
            w[t] = __expf(lrelu(g_as2[sidx] + adst) - fmx) * finv;
        }
        __syncthreads();
        for (int q = 0; q < cnt; q++)
            acc += w[q] * g_h2[(long long)ssrc[q] * HID + t];
        __syncthreads();
    }
    g_out2[(long long)n * HID + t] = acc + b2[t];
}

// ------------------------- global mean pool -------------------------
__global__ void pool_kernel(const void* __restrict__ batch) {
    int n = blockIdx.x, t = threadIdx.x;
    int g = clampi(idx_at(batch, n), NG);
    atomicAdd(&g_pooled[g * HID + t], g_out2[(long long)n * HID + t]);
    if (t == 0) atomicAdd(&g_gcnt[g], 1.0f);
}

// ------------------------- MLP head -------------------------
__global__ void mlp_kernel(const float* __restrict__ Wm1, const float* __restrict__ bm1,
                           const float* __restrict__ Wm2, const float* __restrict__ bm2,
                           float* __restrict__ out) {
    int g = blockIdx.x, t = threadIdx.x;
    __shared__ float p[HID], z[HID];
    float c = fmaxf(g_gcnt[g], 1.0f);
    p[t] = g_pooled[g * HID + t] / c;
    __syncthreads();
    float a = bm1[t];
    #pragma unroll 8
    for (int k = 0; k < HID; k++) a += p[k] * Wm1[k * HID + t];
    z[t] = a > 0.f ? a : 0.f;
    __syncthreads();
    if (t < OC) {
        float o = bm2[t];
        #pragma unroll 8
        for (int k = 0; k < HID; k++) o += z[k] * Wm2[k * OC + t];
        out[g * OC + t] = o;
    }
}

// ------------------------- launch -------------------------
extern "C" void kernel_launch(void* const* d_in, const int* in_sizes, int n_in,
                              void* d_out, int out_size) {
    const float* x    = (const float*)d_in[0];
    const void*  ei   = d_in[1];
    const void*  bat  = d_in[2];
    const float* W1   = (const float*)d_in[3];
    const float* as1  = (const float*)d_in[4];
    const float* ad1  = (const float*)d_in[5];
    const float* b1   = (const float*)d_in[6];
    const float* W2   = (const float*)d_in[7];
    const float* as2  = (const float*)d_in[8];
    const float* ad2  = (const float*)d_in[9];
    const float* b2   = (const float*)d_in[10];
    const float* Wm1  = (const float*)d_in[11];
    const float* bm1  = (const float*)d_in[12];
    const float* Wm2  = (const float*)d_in[13];
    const float* bm2  = (const float*)d_in[14];
    float* out = (float*)d_out;

    // dtype detection + CSR build
    detect_kernel<<<1, 1>>>((const int*)ei);
    zero_kernel<<<(NN + 255) / 256, 256>>>();
    hist_kernel<<<(NET + 255) / 256, 256>>>(ei);
    scan1_kernel<<<SNB, SCH>>>();
    scan2_kernel<<<1, 32>>>();
    scan3_kernel<<<(NN + 255) / 256, 256>>>();
    scatter_kernel<<<(NET + 255) / 256, 256>>>(ei);

    // Layer 1
    {
        dim3 grid(F1 / GBN, (NN + GBM - 1) / GBM);
        gemm1_kernel<<<grid, 256>>>(x, W1);
    }
    att1_kernel<<<NN, 128>>>(as1, ad1);
    agg1_kernel<<<NN, 128>>>(b1);

    // Layer 2
    {
        dim3 grid(HID / GBN, (NN + GBM - 1) / GBM);
        gemm2_kernel<<<grid, 256>>>(W2);
    }
    att2_kernel<<<NN, 128>>>(as2, ad2);
    agg2_kernel<<<NN, 128>>>(b2);

    // Pool + MLP
    pool_kernel<<<NN, HID>>>(bat);
    mlp_kernel<<<NG, HID>>>(Wm1, bm1, Wm2, bm2, out);
}

// round 6
// speedup vs baseline: 2.1928x; 1.1235x over previous
#include <cuda_runtime.h>
#include <cuda_bf16.h>
#include <cuda_fp16.h>

// Problem constants
#define NN      20000        // nodes
#define NE      320000       // raw edges
#define NET     340000       // edges + self loops
#define IN_CH   256
#define HID     128
#define HEADS   4
#define F1      (HEADS*HID)  // 512
#define NG      128          // graphs
#define OC      16
#define NEG     0.2f

// ------------------------- device scratch -------------------------
__device__ __half g_h1h [NN * F1];     // x @ W1 (fp16 for gather)
__device__ float  g_h1b [NN * F1];     // relu(agg1 + b1)  (GEMM2 input, fp32)
__device__ __half g_h2h [NN * HID];    // h1b @ W2 (fp16 for gather)
__device__ float  g_as1 [NN * HEADS];
__device__ float  g_ad1 [NN * HEADS];
__device__ float  g_as2 [NN];
__device__ float  g_ad2 [NN];
__device__ int    g_counts [NN];
__device__ int    g_rowstart[NN + 1];
__device__ int    g_cursor [NN];
__device__ int    g_csrsrc [NET];
__device__ float  g_pooled [NG * HID];
__device__ float  g_gcnt   [NG];
__device__ int    g_idx64;

#define SCH 1024
#define SNB ((NN + SCH - 1) / SCH)     // 20
__device__ int g_bsum[SNB];
__device__ int g_boff[SNB];

// ------------------------- helpers -------------------------
__device__ __forceinline__ float warpMax(float v) {
    #pragma unroll
    for (int o = 16; o > 0; o >>= 1) v = fmaxf(v, __shfl_xor_sync(0xffffffffu, v, o));
    return v;
}
__device__ __forceinline__ float warpSum(float v) {
    #pragma unroll
    for (int o = 16; o > 0; o >>= 1) v += __shfl_xor_sync(0xffffffffu, v, o);
    return v;
}
__device__ __forceinline__ float lrelu(float x) { return x > 0.f ? x : NEG * x; }
__device__ __forceinline__ int clampi(int v, int hi) {
    return v < 0 ? 0 : (v >= hi ? hi - 1 : v);
}
__device__ __forceinline__ int idx_at(const void* p, int i) {
    if (g_idx64) return (int)((const long long*)p)[i];
    return ((const int*)p)[i];
}
__device__ __forceinline__ unsigned f2tf32(float f) {
    unsigned r;
    asm("cvt.rna.tf32.f32 %0, %1;" : "=r"(r) : "f"(f));
    return r;
}
__device__ __forceinline__ void mma_tf32(float* c, unsigned a0, unsigned a1,
                                         unsigned a2, unsigned a3,
                                         unsigned b0, unsigned b1) {
    asm("mma.sync.aligned.m16n8k8.row.col.f32.tf32.tf32.f32 "
        "{%0,%1,%2,%3}, {%4,%5,%6,%7}, {%8,%9}, {%0,%1,%2,%3};"
        : "+f"(c[0]), "+f"(c[1]), "+f"(c[2]), "+f"(c[3])
        : "r"(a0), "r"(a1), "r"(a2), "r"(a3), "r"(b0), "r"(b1));
}
__device__ __forceinline__ void cp16(void* dst, const void* src, int sz) {
    unsigned d = (unsigned)__cvta_generic_to_shared(dst);
    asm volatile("cp.async.ca.shared.global [%0], [%1], 16, %2;"
                 :: "r"(d), "l"(src), "r"(sz));
}
__device__ __forceinline__ void cp_commit() { asm volatile("cp.async.commit_group;"); }
template<int N> __device__ __forceinline__ void cp_wait() {
    asm volatile("cp.async.wait_group %0;" :: "n"(N));
}

// ------------------------- dtype detection -------------------------
__global__ void detect_kernel(const int* __restrict__ ei32) {
    int allzero = 1;
    #pragma unroll 1
    for (int i = 1; i < 128; i += 2)
        if (ei32[i] != 0) { allzero = 0; break; }
    g_idx64 = allzero;
}

// ------------------------- zero scratch -------------------------
__global__ void zero_kernel() {
    int i = blockIdx.x * blockDim.x + threadIdx.x;
    if (i < NN) g_counts[i] = 0;
    if (i < NN * HEADS) { g_as1[i] = 0.f; g_ad1[i] = 0.f; }
    if (i < NN) { g_as2[i] = 0.f; g_ad2[i] = 0.f; }
    if (i < NG * HID) g_pooled[i] = 0.f;
    if (i < NG) g_gcnt[i] = 0.f;
}

// ------------------------- CSR build -------------------------
__global__ void hist_kernel(const void* __restrict__ ei) {
    int i = blockIdx.x * blockDim.x + threadIdx.x;
    if (i >= NET) return;
    int dst = (i < NE) ? clampi(idx_at(ei, NE + i), NN) : (i - NE);
    atomicAdd(&g_counts[dst], 1);
}

__global__ void scan1_kernel() {
    __shared__ int sbuf[SCH];
    int b = blockIdx.x, t = threadIdx.x;
    int i = b * SCH + t;
    int v = (i < NN) ? g_counts[i] : 0;
    sbuf[t] = v;
    __syncthreads();
    #pragma unroll
    for (int off = 1; off < SCH; off <<= 1) {
        int x = (t >= off) ? sbuf[t - off] : 0;
        __syncthreads();
        sbuf[t] += x;
        __syncthreads();
    }
    if (i < NN) g_rowstart[i + 1] = sbuf[t];
    if (t == SCH - 1) g_bsum[b] = sbuf[t];
}

__global__ void scan2_kernel() {
    if (threadIdx.x == 0) {
        int run = 0;
        g_rowstart[0] = 0;
        #pragma unroll
        for (int b = 0; b < SNB; b++) { g_boff[b] = run; run += g_bsum[b]; }
    }
}

__global__ void scan3_kernel() {
    int i = blockIdx.x * blockDim.x + threadIdx.x;
    if (i >= NN) return;
    int fin = g_rowstart[i + 1] + g_boff[i >> 10];
    g_rowstart[i + 1] = fin;
    g_cursor[i] = fin - g_counts[i];
}

__global__ void scatter_kernel(const void* __restrict__ ei) {
    int i = blockIdx.x * blockDim.x + threadIdx.x;
    if (i >= NET) return;
    int src, dst;
    if (i < NE) {
        src = clampi(idx_at(ei, i), NN);
        dst = clampi(idx_at(ei, NE + i), NN);
    } else {
        src = dst = i - NE;
    }
    int pos = atomicAdd(&g_cursor[dst], 1);
    g_csrsrc[pos] = src;
}

// ------------------------- TF32 GEMM, cp.async 3-stage, fused att + fp16 store ------
// C[M,N] = A[M,K] @ B[K,N] (row-major), output to half Ch. N%64==0, K%16==0, M guarded.
// Fused: asOut[row*heads+hd] += sum_c C[row,c]*attS[c] (ditto adOut), hd = col/HID.
#define GBM 128
#define GBN 64
#define GBK 16
#define NSTG 3
#define APAD 4   // As stride 20 -> conflict-free
#define BPAD 8   // Bs stride 72 -> conflict-free

__device__ __forceinline__ void tf32_gemm_fused(const float* __restrict__ A,
                                                const float* __restrict__ B,
                                                __half* __restrict__ Ch,
                                                int M, int N, int K,
                                                const float* __restrict__ attS,
                                                const float* __restrict__ attD,
                                                float* __restrict__ asOut,
                                                float* __restrict__ adOut,
                                                int heads) {
    __shared__ float As[NSTG][GBM][GBK + APAD];
    __shared__ float Bs[NSTG][GBK][GBN + BPAD];

    int tid  = threadIdx.x;
    int lane = tid & 31;
    int warp = tid >> 5;
    int wm = warp & 3;
    int wn = warp >> 2;
    int rowBase = blockIdx.y * GBM;
    int colBase = blockIdx.x * GBN;
    int q  = lane & 3;
    int r0 = lane >> 2;

    int aRow = tid >> 2;            // 0..63
    int aCol = (tid & 3) * 4;       // 0,4,8,12
    int bRow = tid >> 4;            // 0..15
    int bCol = (tid & 15) * 4;      // 0..60

    int nIter = K / GBK;
    float acc[2][4][4] = {};

    // prefetch stages
    #pragma unroll
    for (int pf = 0; pf < NSTG - 1; pf++) {
        if (pf < nIter) {
            int k0 = pf * GBK;
            #pragma unroll
            for (int i = 0; i < 2; i++) {
                int row = aRow + 64 * i;
                int gr = rowBase + row;
                const float* src = (gr < M) ? &A[(long long)gr * K + k0 + aCol] : A;
                cp16(&As[pf][row][aCol], src, (gr < M) ? 16 : 0);
            }
            cp16(&Bs[pf][bRow][bCol], &B[(long long)(k0 + bRow) * N + colBase + bCol], 16);
        }
        cp_commit();
    }

    for (int it = 0; it < nIter; it++) {
        int cur = it % NSTG;
        // prefetch it + NSTG-1
        {
            int ip = it + NSTG - 1;
            if (ip < nIter) {
                int st = ip % NSTG;
                int k0 = ip * GBK;
                #pragma unroll
                for (int i = 0; i < 2; i++) {
                    int row = aRow + 64 * i;
                    int gr = rowBase + row;
                    const float* src = (gr < M) ? &A[(long long)gr * K + k0 + aCol] : A;
                    cp16(&As[st][row][aCol], src, (gr < M) ? 16 : 0);
                }
                cp16(&Bs[st][bRow][bCol], &B[(long long)(k0 + bRow) * N + colBase + bCol], 16);
            }
            cp_commit();
        }
        cp_wait<NSTG - 1>();
        __syncthreads();

        #pragma unroll
        for (int kk = 0; kk < 2; kk++) {
            int kb = kk * 8;
            unsigned a[2][4], b[4][2];
            #pragma unroll
            for (int mf = 0; mf < 2; mf++) {
                int mrow = wm * 32 + mf * 16 + r0;
                a[mf][0] = f2tf32(As[cur][mrow    ][kb + q    ]);
                a[mf][1] = f2tf32(As[cur][mrow + 8][kb + q    ]);
                a[mf][2] = f2tf32(As[cur][mrow    ][kb + q + 4]);
                a[mf][3] = f2tf32(As[cur][mrow + 8][kb + q + 4]);
            }
            #pragma unroll
            for (int nf = 0; nf < 4; nf++) {
                int ncol = wn * 32 + nf * 8 + r0;
                b[nf][0] = f2tf32(Bs[cur][kb + q    ][ncol]);
                b[nf][1] = f2tf32(Bs[cur][kb + q + 4][ncol]);
            }
            #pragma unroll
            for (int mf = 0; mf < 2; mf++)
                #pragma unroll
                for (int nf = 0; nf < 4; nf++)
                    mma_tf32(acc[mf][nf], a[mf][0], a[mf][1], a[mf][2], a[mf][3],
                             b[nf][0], b[nf][1]);
        }
        __syncthreads();
    }

    // ---- fused epilogue ----
    int hd = (colBase + wn * 32) / HID;
    float attSv[8], attDv[8];
    #pragma unroll
    for (int nf = 0; nf < 4; nf++) {
        int gc = colBase + wn * 32 + nf * 8 + 2 * q;
        attSv[nf*2]   = attS[gc];     attSv[nf*2+1] = attS[gc+1];
        attDv[nf*2]   = attD[gc];     attDv[nf*2+1] = attD[gc+1];
    }
    #pragma unroll
    for (int mf = 0; mf < 2; mf++) {
        int gr0 = rowBase + wm * 32 + mf * 16 + r0;
        float psT = 0.f, pdT = 0.f, psB = 0.f, pdB = 0.f;
        #pragma unroll
        for (int nf = 0; nf < 4; nf++) {
            psT += acc[mf][nf][0]*attSv[nf*2] + acc[mf][nf][1]*attSv[nf*2+1];
            pdT += acc[mf][nf][0]*attDv[nf*2] + acc[mf][nf][1]*attDv[nf*2+1];
            psB += acc[mf][nf][2]*attSv[nf*2] + acc[mf][nf][3]*attSv[nf*2+1];
            pdB += acc[mf][nf][2]*attDv[nf*2] + acc[mf][nf][3]*attDv[nf*2+1];
        }
        #pragma unroll
        for (int o = 1; o < 4; o <<= 1) {
            psT += __shfl_xor_sync(0xffffffffu, psT, o);
            pdT += __shfl_xor_sync(0xffffffffu, pdT, o);
            psB += __shfl_xor_sync(0xffffffffu, psB, o);
            pdB += __shfl_xor_sync(0xffffffffu, pdB, o);
        }
        if (q == 0) {
            if (gr0 < M)     { atomicAdd(&asOut[gr0*heads+hd], psT);
                               atomicAdd(&adOut[gr0*heads+hd], pdT); }
            if (gr0 + 8 < M) { atomicAdd(&asOut[(gr0+8)*heads+hd], psB);
                               atomicAdd(&adOut[(gr0+8)*heads+hd], pdB); }
        }
        #pragma unroll
        for (int nf = 0; nf < 4; nf++) {
            int gc = colBase + wn * 32 + nf * 8 + 2 * q;
            if (gr0 < M)
                *(__half2*)&Ch[(long long)gr0 * N + gc] =
                    __floats2half2_rn(acc[mf][nf][0], acc[mf][nf][1]);
            if (gr0 + 8 < M)
                *(__half2*)&Ch[(long long)(gr0 + 8) * N + gc] =
                    __floats2half2_rn(acc[mf][nf][2], acc[mf][nf][3]);
        }
    }
}

__global__ __launch_bounds__(256) void gemm1_kernel(const float* __restrict__ x,
                                                    const float* __restrict__ W1,
                                                    const float* __restrict__ as1,
                                                    const float* __restrict__ ad1) {
    tf32_gemm_fused(x, W1, g_h1h, NN, F1, IN_CH, as1, ad1, g_as1, g_ad1, HEADS);
}

__global__ __launch_bounds__(256) void gemm2_kernel(const float* __restrict__ W2,
                                                    const float* __restrict__ as2,
                                                    const float* __restrict__ ad2) {
    tf32_gemm_fused(g_h1b, W2, g_h2h, NN, HID, F1, as2, ad2, g_as2, g_ad2, 1);
}

// ------------------------- layer-1 aggregation -------------------------
__global__ __launch_bounds__(128) void agg1_kernel(const float* __restrict__ b1) {
    int n = blockIdx.x, t = threadIdx.x;
    int warp = t >> 5, lane = t & 31;
    int beg = g_rowstart[n], end = g_rowstart[n + 1];

    __shared__ float s_adst[HEADS];
    if (t < HEADS) s_adst[t] = g_ad1[n * HEADS + t];
    __syncthreads();

    float m[HEADS] = {-1e30f, -1e30f, -1e30f, -1e30f};
    for (int j = beg + t; j < end; j += 128) {
        int s = g_csrsrc[j];
        #pragma unroll
        for (int h = 0; h < HEADS; h++) {
            float e = lrelu(g_as1[s * HEADS + h] + s_adst[h]);
            m[h] = fmaxf(m[h], e);
        }
    }
    __shared__ float wr[4][HEADS];
    #pragma unroll
    for (int h = 0; h < HEADS; h++) m[h] = warpMax(m[h]);
    if (lane == 0) {
        #pragma unroll
        for (int h = 0; h < HEADS; h++) wr[warp][h] = m[h];
    }
    __syncthreads();
    __shared__ float fmx[HEADS];
    if (t < HEADS) fmx[t] = fmaxf(fmaxf(wr[0][t], wr[1][t]), fmaxf(wr[2][t], wr[3][t]));
    __syncthreads();

    float ssum[HEADS] = {0, 0, 0, 0};
    for (int j = beg + t; j < end; j += 128) {
        int s = g_csrsrc[j];
        #pragma unroll
        for (int h = 0; h < HEADS; h++) {
            float e = lrelu(g_as1[s * HEADS + h] + s_adst[h]);
            ssum[h] += __expf(e - fmx[h]);
        }
    }
    #pragma unroll
    for (int h = 0; h < HEADS; h++) ssum[h] = warpSum(ssum[h]);
    if (lane == 0) {
        #pragma unroll
        for (int h = 0; h < HEADS; h++) wr[warp][h] = ssum[h];
    }
    __syncthreads();
    __shared__ float finv[HEADS];
    if (t < HEADS) finv[t] = 1.f / (wr[0][t] + wr[1][t] + wr[2][t] + wr[3][t]);
    __syncthreads();

    __shared__ float w[32 * HEADS];
    __shared__ int ssrc[32];
    float acc[HEADS] = {0, 0, 0, 0};
    for (int base = beg; base < end; base += 32) {
        int cnt = min(32, end - base);
        int je = t >> 2, h = t & 3;
        if (je < cnt) {
            int s = g_csrsrc[base + je];
            if (h == 0) ssrc[je] = s;
            float e = lrelu(g_as1[s * HEADS + h] + s_adst[h]);
            w[je * HEADS + h] = __expf(e - fmx[h]) * finv[h];
        }
        __syncthreads();
        for (int qq = 0; qq < cnt; qq++) {
            int s = ssrc[qq];
            const __half* hp = &g_h1h[(long long)s * F1];
            #pragma unroll
            for (int hh = 0; hh < HEADS; hh++)
                acc[hh] += w[qq * HEADS + hh] * __half2float(hp[hh * HID + t]);
        }
        __syncthreads();
    }
    #pragma unroll
    for (int h = 0; h < HEADS; h++) {
        float v = acc[h] + b1[h * HID + t];
        g_h1b[(long long)n * F1 + h * HID + t] = v > 0.f ? v : 0.f;
    }
}

// ------------------------- layer-2 aggregation (+ fused mean-pool accumulate) ------
__global__ __launch_bounds__(128) void agg2_kernel(const float* __restrict__ b2,
                                                   const void* __restrict__ batch) {
    int n = blockIdx.x, t = threadIdx.x;
    int warp = t >> 5, lane = t & 31;
    int beg = g_rowstart[n], end = g_rowstart[n + 1];
    float adst = g_ad2[n];

    float m = -1e30f;
    for (int j = beg + t; j < end; j += 128)
        m = fmaxf(m, lrelu(g_as2[g_csrsrc[j]] + adst));
    __shared__ float wr[4];
    m = warpMax(m);
    if (lane == 0) wr[warp] = m;
    __syncthreads();
    __shared__ float fmx, finv;
    if (t == 0) fmx = fmaxf(fmaxf(wr[0], wr[1]), fmaxf(wr[2], wr[3]));
    __syncthreads();

    float s = 0.f;
    for (int j = beg + t; j < end; j += 128)
        s += __expf(lrelu(g_as2[g_csrsrc[j]] + adst) - fmx);
    s = warpSum(s);
    if (lane == 0) wr[warp] = s;
    __syncthreads();
    if (t == 0) finv = 1.f / (wr[0] + wr[1] + wr[2] + wr[3]);
    __syncthreads();

    __shared__ float w[128];
    __shared__ int ssrc[128];
    float acc = 0.f;
    for (int base = beg; base < end; base += 128) {
        int cnt = min(128, end - base);
        if (t < cnt) {
            int sidx = g_csrsrc[base + t];
            ssrc[t] = sidx;
            w[t] = __expf(lrelu(g_as2[sidx] + adst) - fmx) * finv;
        }
        __syncthreads();
        for (int qq = 0; qq < cnt; qq++)
            acc += w[qq] * __half2float(g_h2h[(long long)ssrc[qq] * HID + t]);
        __syncthreads();
    }
    // fused pool
    int g = clampi(idx_at(batch, n), NG);
    atomicAdd(&g_pooled[g * HID + t], acc + b2[t]);
    if (t == 0) atomicAdd(&g_gcnt[g], 1.0f);
}

// ------------------------- MLP head -------------------------
__global__ void mlp_kernel(const float* __restrict__ Wm1, const float* __restrict__ bm1,
                           const float* __restrict__ Wm2, const float* __restrict__ bm2,
                           float* __restrict__ out) {
    int g = blockIdx.x, t = threadIdx.x;
    __shared__ float p[HID], z[HID];
    float c = fmaxf(g_gcnt[g], 1.0f);
    p[t] = g_pooled[g * HID + t] / c;
    __syncthreads();
    float a = bm1[t];
    #pragma unroll 8
    for (int k = 0; k < HID; k++) a += p[k] * Wm1[k * HID + t];
    z[t] = a > 0.f ? a : 0.f;
    __syncthreads();
    if (t < OC) {
        float o = bm2[t];
        #pragma unroll 8
        for (int k = 0; k < HID; k++) o += z[k] * Wm2[k * OC + t];
        out[g * OC + t] = o;
    }
}

// ------------------------- launch -------------------------
extern "C" void kernel_launch(void* const* d_in, const int* in_sizes, int n_in,
                              void* d_out, int out_size) {
    const float* x    = (const float*)d_in[0];
    const void*  ei   = d_in[1];
    const void*  bat  = d_in[2];
    const float* W1   = (const float*)d_in[3];
    const float* as1  = (const float*)d_in[4];
    const float* ad1  = (const float*)d_in[5];
    const float* b1   = (const float*)d_in[6];
    const float* W2   = (const float*)d_in[7];
    const float* as2  = (const float*)d_in[8];
    const float* ad2  = (const float*)d_in[9];
    const float* b2   = (const float*)d_in[10];
    const float* Wm1  = (const float*)d_in[11];
    const float* bm1  = (const float*)d_in[12];
    const float* Wm2  = (const float*)d_in[13];
    const float* bm2  = (const float*)d_in[14];
    float* out = (float*)d_out;

    detect_kernel<<<1, 1>>>((const int*)ei);
    zero_kernel<<<(NN * HEADS + 255) / 256, 256>>>();
    hist_kernel<<<(NET + 255) / 256, 256>>>(ei);
    scan1_kernel<<<SNB, SCH>>>();
    scan2_kernel<<<1, 32>>>();
    scan3_kernel<<<(NN + 255) / 256, 256>>>();
    scatter_kernel<<<(NET + 255) / 256, 256>>>(ei);

    // Layer 1: GEMM + fused att1 + fp16 store
    {
        dim3 grid(F1 / GBN, (NN + GBM - 1) / GBM);
        gemm1_kernel<<<grid, 256>>>(x, W1, as1, ad1);
    }
    agg1_kernel<<<NN, 128>>>(b1);

    // Layer 2: GEMM + fused att2 + fp16 store
    {
        dim3 grid(HID / GBN, (NN + GBM - 1) / GBM);
        gemm2_kernel<<<grid, 256>>>(W2, as2, ad2);
    }
    agg2_kernel<<<NN, 128>>>(b2, bat);

    mlp_kernel<<<NG, HID>>>(Wm1, bm1, Wm2, bm2, out);
}

// round 7
// speedup vs baseline: 2.5274x; 1.1526x over previous
#include <cuda_runtime.h>
#include <cuda_bf16.h>
#include <cuda_fp16.h>

// Problem constants
#define NN      20000        // nodes
#define NE      320000       // raw edges
#define NET     340000       // edges + self loops
#define IN_CH   256
#define HID     128
#define HEADS   4
#define F1      (HEADS*HID)  // 512
#define NG      128          // graphs
#define OC      16
#define NEG     0.2f

// ------------------------- device scratch -------------------------
__device__ __half g_h1h [NN * F1];     // x @ W1 (fp16 for gather)
__device__ float  g_h1b [NN * F1];     // relu(agg1 + b1)  (GEMM2 input, fp32)
__device__ __half g_h2h [NN * HID];    // h1b @ W2 (fp16 for gather)
__device__ float  g_as1 [NN * HEADS];
__device__ float  g_ad1 [NN * HEADS];
__device__ float  g_as2 [NN];
__device__ float  g_ad2 [NN];
__device__ int    g_counts [NN];
__device__ int    g_rowstart[NN + 1];
__device__ int    g_cursor [NN];
__device__ int    g_csrsrc [NET];
__device__ float  g_pooled [NG * HID];
__device__ float  g_gcnt   [NG];
__device__ int    g_idx64;

#define SCH 1024
#define SNB ((NN + SCH - 1) / SCH)     // 20
__device__ int g_bsum[SNB];
__device__ int g_boff[SNB];

// ------------------------- helpers -------------------------
__device__ __forceinline__ float warpSum(float v) {
    #pragma unroll
    for (int o = 16; o > 0; o >>= 1) v += __shfl_xor_sync(0xffffffffu, v, o);
    return v;
}
__device__ __forceinline__ float lrelu(float x) { return x > 0.f ? x : NEG * x; }
__device__ __forceinline__ int clampi(int v, int hi) {
    return v < 0 ? 0 : (v >= hi ? hi - 1 : v);
}
__device__ __forceinline__ int idx_at(const void* p, int i) {
    if (g_idx64) return (int)((const long long*)p)[i];
    return ((const int*)p)[i];
}
__device__ __forceinline__ unsigned f2tf32(float f) {
    unsigned r;
    asm("cvt.rna.tf32.f32 %0, %1;" : "=r"(r) : "f"(f));
    return r;
}
__device__ __forceinline__ void mma_tf32(float* c, unsigned a0, unsigned a1,
                                         unsigned a2, unsigned a3,
                                         unsigned b0, unsigned b1) {
    asm("mma.sync.aligned.m16n8k8.row.col.f32.tf32.tf32.f32 "
        "{%0,%1,%2,%3}, {%4,%5,%6,%7}, {%8,%9}, {%0,%1,%2,%3};"
        : "+f"(c[0]), "+f"(c[1]), "+f"(c[2]), "+f"(c[3])
        : "r"(a0), "r"(a1), "r"(a2), "r"(a3), "r"(b0), "r"(b1));
}
__device__ __forceinline__ void cp16(void* dst, const void* src, int sz) {
    unsigned d = (unsigned)__cvta_generic_to_shared(dst);
    asm volatile("cp.async.ca.shared.global [%0], [%1], 16, %2;"
                 :: "r"(d), "l"(src), "r"(sz));
}
__device__ __forceinline__ void cp_commit() { asm volatile("cp.async.commit_group;"); }
template<int N> __device__ __forceinline__ void cp_wait() {
    asm volatile("cp.async.wait_group %0;" :: "n"(N));
}

// ------------------------- dtype detection -------------------------
__global__ void detect_kernel(const int* __restrict__ ei32) {
    int allzero = 1;
    #pragma unroll 1
    for (int i = 1; i < 128; i += 2)
        if (ei32[i] != 0) { allzero = 0; break; }
    g_idx64 = allzero;
}

// ------------------------- zero scratch -------------------------
__global__ void zero_kernel() {
    int i = blockIdx.x * blockDim.x + threadIdx.x;
    if (i < NN) g_counts[i] = 0;
    if (i < NN * HEADS) { g_as1[i] = 0.f; g_ad1[i] = 0.f; }
    if (i < NN) { g_as2[i] = 0.f; g_ad2[i] = 0.f; }
    if (i < NG * HID) g_pooled[i] = 0.f;
    if (i < NG) g_gcnt[i] = 0.f;
}

// ------------------------- CSR build -------------------------
__global__ void hist_kernel(const void* __restrict__ ei) {
    int i = blockIdx.x * blockDim.x + threadIdx.x;
    if (i >= NET) return;
    int dst = (i < NE) ? clampi(idx_at(ei, NE + i), NN) : (i - NE);
    atomicAdd(&g_counts[dst], 1);
}

__global__ void scan1_kernel() {
    __shared__ int sbuf[SCH];
    int b = blockIdx.x, t = threadIdx.x;
    int i = b * SCH + t;
    int v = (i < NN) ? g_counts[i] : 0;
    sbuf[t] = v;
    __syncthreads();
    #pragma unroll
    for (int off = 1; off < SCH; off <<= 1) {
        int x = (t >= off) ? sbuf[t - off] : 0;
        __syncthreads();
        sbuf[t] += x;
        __syncthreads();
    }
    if (i < NN) g_rowstart[i + 1] = sbuf[t];
    if (t == SCH - 1) g_bsum[b] = sbuf[t];
}

__global__ void scan2_kernel() {
    if (threadIdx.x == 0) {
        int run = 0;
        g_rowstart[0] = 0;
        #pragma unroll
        for (int b = 0; b < SNB; b++) { g_boff[b] = run; run += g_bsum[b]; }
    }
}

__global__ void scan3_kernel() {
    int i = blockIdx.x * blockDim.x + threadIdx.x;
    if (i >= NN) return;
    int fin = g_rowstart[i + 1] + g_boff[i >> 10];
    g_rowstart[i + 1] = fin;
    g_cursor[i] = fin - g_counts[i];
}

__global__ void scatter_kernel(const void* __restrict__ ei) {
    int i = blockIdx.x * blockDim.x + threadIdx.x;
    if (i >= NET) return;
    int src, dst;
    if (i < NE) {
        src = clampi(idx_at(ei, i), NN);
        dst = clampi(idx_at(ei, NE + i), NN);
    } else {
        src = dst = i - NE;
    }
    int pos = atomicAdd(&g_cursor[dst], 1);
    g_csrsrc[pos] = src;
}

// ------------------------- TF32 GEMM, cp.async 3-stage, fused att + fp16 store ------
#define GBM 128
#define GBN 64
#define GBK 16
#define NSTG 3
#define APAD 4
#define BPAD 8

__device__ __forceinline__ void tf32_gemm_fused(const float* __restrict__ A,
                                                const float* __restrict__ B,
                                                __half* __restrict__ Ch,
                                                int M, int N, int K,
                                                const float* __restrict__ attS,
                                                const float* __restrict__ attD,
                                                float* __restrict__ asOut,
                                                float* __restrict__ adOut,
                                                int heads) {
    __shared__ float As[NSTG][GBM][GBK + APAD];
    __shared__ float Bs[NSTG][GBK][GBN + BPAD];

    int tid  = threadIdx.x;
    int lane = tid & 31;
    int warp = tid >> 5;
    int wm = warp & 3;
    int wn = warp >> 2;
    int rowBase = blockIdx.y * GBM;
    int colBase = blockIdx.x * GBN;
    int q  = lane & 3;
    int r0 = lane >> 2;

    int aRow = tid >> 2;            // 0..63
    int aCol = (tid & 3) * 4;       // 0,4,8,12
    int bRow = tid >> 4;            // 0..15
    int bCol = (tid & 15) * 4;      // 0..60

    int nIter = K / GBK;
    float acc[2][4][4] = {};

    #pragma unroll
    for (int pf = 0; pf < NSTG - 1; pf++) {
        if (pf < nIter) {
            int k0 = pf * GBK;
            #pragma unroll
            for (int i = 0; i < 2; i++) {
                int row = aRow + 64 * i;
                int gr = rowBase + row;
                const float* src = (gr < M) ? &A[(long long)gr * K + k0 + aCol] : A;
                cp16(&As[pf][row][aCol], src, (gr < M) ? 16 : 0);
            }
            cp16(&Bs[pf][bRow][bCol], &B[(long long)(k0 + bRow) * N + colBase + bCol], 16);
        }
        cp_commit();
    }

    for (int it = 0; it < nIter; it++) {
        int cur = it % NSTG;
        {
            int ip = it + NSTG - 1;
            if (ip < nIter) {
                int st = ip % NSTG;
                int k0 = ip * GBK;
                #pragma unroll
                for (int i = 0; i < 2; i++) {
                    int row = aRow + 64 * i;
                    int gr = rowBase + row;
                    const float* src = (gr < M) ? &A[(long long)gr * K + k0 + aCol] : A;
                    cp16(&As[st][row][aCol], src, (gr < M) ? 16 : 0);
                }
                cp16(&Bs[st][bRow][bCol], &B[(long long)(k0 + bRow) * N + colBase + bCol], 16);
            }
            cp_commit();
        }
        cp_wait<NSTG - 1>();
        __syncthreads();

        #pragma unroll
        for (int kk = 0; kk < 2; kk++) {
            int kb = kk * 8;
            unsigned a[2][4], b[4][2];
            #pragma unroll
            for (int mf = 0; mf < 2; mf++) {
                int mrow = wm * 32 + mf * 16 + r0;
                a[mf][0] = f2tf32(As[cur][mrow    ][kb + q    ]);
                a[mf][1] = f2tf32(As[cur][mrow + 8][kb + q    ]);
                a[mf][2] = f2tf32(As[cur][mrow    ][kb + q + 4]);
                a[mf][3] = f2tf32(As[cur][mrow + 8][kb + q + 4]);
            }
            #pragma unroll
            for (int nf = 0; nf < 4; nf++) {
                int ncol = wn * 32 + nf * 8 + r0;
                b[nf][0] = f2tf32(Bs[cur][kb + q    ][ncol]);
                b[nf][1] = f2tf32(Bs[cur][kb + q + 4][ncol]);
            }
            #pragma unroll
            for (int mf = 0; mf < 2; mf++)
                #pragma unroll
                for (int nf = 0; nf < 4; nf++)
                    mma_tf32(acc[mf][nf], a[mf][0], a[mf][1], a[mf][2], a[mf][3],
                             b[nf][0], b[nf][1]);
        }
        __syncthreads();
    }

    // ---- fused epilogue ----
    int hd = (colBase + wn * 32) / HID;
    float attSv[8], attDv[8];
    #pragma unroll
    for (int nf = 0; nf < 4; nf++) {
        int gc = colBase + wn * 32 + nf * 8 + 2 * q;
        attSv[nf*2]   = attS[gc];     attSv[nf*2+1] = attS[gc+1];
        attDv[nf*2]   = attD[gc];     attDv[nf*2+1] = attD[gc+1];
    }
    #pragma unroll
    for (int mf = 0; mf < 2; mf++) {
        int gr0 = rowBase + wm * 32 + mf * 16 + r0;
        float psT = 0.f, pdT = 0.f, psB = 0.f, pdB = 0.f;
        #pragma unroll
        for (int nf = 0; nf < 4; nf++) {
            psT += acc[mf][nf][0]*attSv[nf*2] + acc[mf][nf][1]*attSv[nf*2+1];
            pdT += acc[mf][nf][0]*attDv[nf*2] + acc[mf][nf][1]*attDv[nf*2+1];
            psB += acc[mf][nf][2]*attSv[nf*2] + acc[mf][nf][3]*attSv[nf*2+1];
            pdB += acc[mf][nf][2]*attDv[nf*2] + acc[mf][nf][3]*attDv[nf*2+1];
        }
        #pragma unroll
        for (int o = 1; o < 4; o <<= 1) {
            psT += __shfl_xor_sync(0xffffffffu, psT, o);
            pdT += __shfl_xor_sync(0xffffffffu, pdT, o);
            psB += __shfl_xor_sync(0xffffffffu, psB, o);
            pdB += __shfl_xor_sync(0xffffffffu, pdB, o);
        }
        if (q == 0) {
            if (gr0 < M)     { atomicAdd(&asOut[gr0*heads+hd], psT);
                               atomicAdd(&adOut[gr0*heads+hd], pdT); }
            if (gr0 + 8 < M) { atomicAdd(&asOut[(gr0+8)*heads+hd], psB);
                               atomicAdd(&adOut[(gr0+8)*heads+hd], pdB); }
        }
        #pragma unroll
        for (int nf = 0; nf < 4; nf++) {
            int gc = colBase + wn * 32 + nf * 8 + 2 * q;
            if (gr0 < M)
                *(__half2*)&Ch[(long long)gr0 * N + gc] =
                    __floats2half2_rn(acc[mf][nf][0], acc[mf][nf][1]);
            if (gr0 + 8 < M)
                *(__half2*)&Ch[(long long)(gr0 + 8) * N + gc] =
                    __floats2half2_rn(acc[mf][nf][2], acc[mf][nf][3]);
        }
    }
}

__global__ __launch_bounds__(256) void gemm1_kernel(const float* __restrict__ x,
                                                    const float* __restrict__ W1,
                                                    const float* __restrict__ as1,
                                                    const float* __restrict__ ad1) {
    tf32_gemm_fused(x, W1, g_h1h, NN, F1, IN_CH, as1, ad1, g_as1, g_ad1, HEADS);
}

__global__ __launch_bounds__(256) void gemm2_kernel(const float* __restrict__ W2,
                                                    const float* __restrict__ as2,
                                                    const float* __restrict__ ad2) {
    tf32_gemm_fused(g_h1b, W2, g_h2h, NN, HID, F1, as2, ad2, g_as2, g_ad2, 1);
}

// ------------------------- layer-1 aggregation: single pass, vectorized ------
// Block 128. Thread t owns cols 4t..4t+3 (head = t>>5). Unnormalized accumulate,
// divide by Σw at the end (identical to softmax with max-shift removed).
__global__ __launch_bounds__(128) void agg1_kernel(const float* __restrict__ b1) {
    int n = blockIdx.x, t = threadIdx.x;
    int beg = g_rowstart[n], end = g_rowstart[n + 1];
    int head = t >> 5;

    float4 adst = *(const float4*)&g_ad1[n * HEADS];

    __shared__ float4 s_w[32];
    __shared__ int    ssrc[32];
    __shared__ float  s_finv[HEADS];

    float acc0 = 0.f, acc1 = 0.f, acc2 = 0.f, acc3 = 0.f;
    float4 dsum = make_float4(0.f, 0.f, 0.f, 0.f);

    for (int base = beg; base < end; base += 32) {
        int cnt = min(32, end - base);
        __syncthreads();
        if (t < cnt) {
            int s = g_csrsrc[base + t];
            ssrc[t] = s;
            float4 a = *(const float4*)&g_as1[s * HEADS];
            float4 w;
            w.x = __expf(lrelu(a.x + adst.x));
            w.y = __expf(lrelu(a.y + adst.y));
            w.z = __expf(lrelu(a.z + adst.z));
            w.w = __expf(lrelu(a.w + adst.w));
            s_w[t] = w;
            dsum.x += w.x; dsum.y += w.y; dsum.z += w.z; dsum.w += w.w;
        }
        __syncthreads();
        for (int qq = 0; qq < cnt; qq++) {
            int s = ssrc[qq];
            float wq = ((const float*)&s_w[qq])[head];   // warp-uniform broadcast
            uint2 hv = *(const uint2*)&g_h1h[(long long)s * F1 + 4 * t];
            float2 f01 = __half22float2(*(__half2*)&hv.x);
            float2 f23 = __half22float2(*(__half2*)&hv.y);
            acc0 += wq * f01.x; acc1 += wq * f01.y;
            acc2 += wq * f23.x; acc3 += wq * f23.y;
        }
    }
    // dsum partials live in warp 0 only (t<32)
    dsum.x = warpSum(dsum.x); dsum.y = warpSum(dsum.y);
    dsum.z = warpSum(dsum.z); dsum.w = warpSum(dsum.w);
    if (t == 0) {
        s_finv[0] = 1.f / dsum.x; s_finv[1] = 1.f / dsum.y;
        s_finv[2] = 1.f / dsum.z; s_finv[3] = 1.f / dsum.w;
    }
    __syncthreads();
    float fin = s_finv[head];
    float4 bv = *(const float4*)&b1[4 * t];
    float4 o;
    o.x = fmaxf(acc0 * fin + bv.x, 0.f);
    o.y = fmaxf(acc1 * fin + bv.y, 0.f);
    o.z = fmaxf(acc2 * fin + bv.z, 0.f);
    o.w = fmaxf(acc3 * fin + bv.w, 0.f);
    *(float4*)&g_h1b[(long long)n * F1 + 4 * t] = o;
}

// ------------------------- layer-2 aggregation: single pass + fused pool ------
// Block 128 = 2 groups x 64 threads; group g processes edges q = g, g+2, ...
// Thread (g, c) owns cols 2c, 2c+1 via half2 loads.
__global__ __launch_bounds__(128) void agg2_kernel(const float* __restrict__ b2,
                                                   const void* __restrict__ batch) {
    int n = blockIdx.x, t = threadIdx.x;
    int beg = g_rowstart[n], end = g_rowstart[n + 1];
    float adst = g_ad2[n];
    int grp = t >> 6;
    int c   = t & 63;

    __shared__ float s_w[64];
    __shared__ int   ssrc[64];
    __shared__ float s_accB[HID];
    __shared__ float wr2[2];

    float2 acc = make_float2(0.f, 0.f);
    float dsum = 0.f;

    for (int base = beg; base < end; base += 64) {
        int cnt = min(64, end - base);
        __syncthreads();
        if (t < cnt) {
            int s = g_csrsrc[base + t];
            ssrc[t] = s;
            float w = __expf(lrelu(g_as2[s] + adst));
            s_w[t] = w;
            dsum += w;
        }
        __syncthreads();
        for (int qq = grp; qq < cnt; qq += 2) {
            int s = ssrc[qq];
            float w = s_w[qq];
            float2 f = __half22float2(*(const __half2*)&g_h2h[(long long)s * HID + 2 * c]);
            acc.x += w * f.x; acc.y += w * f.y;
        }
    }
    dsum = warpSum(dsum);                       // partials only in warps 0,1
    if ((t & 31) == 0 && t < 64) wr2[t >> 5] = dsum;
    if (grp == 1) { s_accB[2 * c] = acc.x; s_accB[2 * c + 1] = acc.y; }
    __syncthreads();
    if (grp == 0) {
        float di = 1.f / (wr2[0] + wr2[1]);
        float o0 = (acc.x + s_accB[2 * c])     * di + b2[2 * c];
        float o1 = (acc.y + s_accB[2 * c + 1]) * di + b2[2 * c + 1];
        int g = clampi(idx_at(batch, n), NG);
        atomicAdd(&g_pooled[g * HID + 2 * c],     o0);
        atomicAdd(&g_pooled[g * HID + 2 * c + 1], o1);
        if (t == 0) atomicAdd(&g_gcnt[g], 1.0f);
    }
}

// ------------------------- MLP head -------------------------
__global__ void mlp_kernel(const float* __restrict__ Wm1, const float* __restrict__ bm1,
                           const float* __restrict__ Wm2, const float* __restrict__ bm2,
                           float* __restrict__ out) {
    int g = blockIdx.x, t = threadIdx.x;
    __shared__ float p[HID], z[HID];
    float c = fmaxf(g_gcnt[g], 1.0f);
    p[t] = g_pooled[g * HID + t] / c;
    __syncthreads();
    float a = bm1[t];
    #pragma unroll 8
    for (int k = 0; k < HID; k++) a += p[k] * Wm1[k * HID + t];
    z[t] = a > 0.f ? a : 0.f;
    __syncthreads();
    if (t < OC) {
        float o = bm2[t];
        #pragma unroll 8
        for (int k = 0; k < HID; k++) o += z[k] * Wm2[k * OC + t];
        out[g * OC + t] = o;
    }
}

// ------------------------- launch -------------------------
extern "C" void kernel_launch(void* const* d_in, const int* in_sizes, int n_in,
                              void* d_out, int out_size) {
    const float* x    = (const float*)d_in[0];
    const void*  ei   = d_in[1];
    const void*  bat  = d_in[2];
    const float* W1   = (const float*)d_in[3];
    const float* as1  = (const float*)d_in[4];
    const float* ad1  = (const float*)d_in[5];
    const float* b1   = (const float*)d_in[6];
    const float* W2   = (const float*)d_in[7];
    const float* as2  = (const float*)d_in[8];
    const float* ad2  = (const float*)d_in[9];
    const float* b2   = (const float*)d_in[10];
    const float* Wm1  = (const float*)d_in[11];
    const float* bm1  = (const float*)d_in[12];
    const float* Wm2  = (const float*)d_in[13];
    const float* bm2  = (const float*)d_in[14];
    float* out = (float*)d_out;

    detect_kernel<<<1, 1>>>((const int*)ei);
    zero_kernel<<<(NN * HEADS + 255) / 256, 256>>>();
    hist_kernel<<<(NET + 255) / 256, 256>>>(ei);
    scan1_kernel<<<SNB, SCH>>>();
    scan2_kernel<<<1, 32>>>();
    scan3_kernel<<<(NN + 255) / 256, 256>>>();
    scatter_kernel<<<(NET + 255) / 256, 256>>>(ei);

    // Layer 1
    {
        dim3 grid(F1 / GBN, (NN + GBM - 1) / GBM);
        gemm1_kernel<<<grid, 256>>>(x, W1, as1, ad1);
    }
    agg1_kernel<<<NN, 128>>>(b1);

    // Layer 2
    {
        dim3 grid(HID / GBN, (NN + GBM - 1) / GBM);
        gemm2_kernel<<<grid, 256>>>(W2, as2, ad2);
    }
    agg2_kernel<<<NN, 128>>>(b2, bat);

    mlp_kernel<<<NG, HID>>>(Wm1, bm1, Wm2, bm2, out);
}

// round 12
// speedup vs baseline: 2.5995x; 1.0285x over previous
#include <cuda_runtime.h>
#include <cuda_bf16.h>
#include <cuda_fp16.h>

// Problem constants
#define NN      20000        // nodes
#define NE      320000       // raw edges
#define NET     340000       // edges + self loops
#define IN_CH   256
#define HID     128
#define HEADS   4
#define F1      (HEADS*HID)  // 512
#define NG      128          // graphs
#define OC      16
#define NEG     0.2f

// ------------------------- device scratch -------------------------
__device__ __half g_h1h [NN * F1];     // x @ W1 (fp16 for gather)
__device__ float  g_h1b [NN * F1];     // relu(agg1 + b1)  (GEMM2 input, fp32)
__device__ __half g_h2h [NN * HID];    // h1b @ W2 (fp16 for gather)
__device__ float  g_as1 [NN * HEADS];
__device__ float  g_ad1 [NN * HEADS];
__device__ float  g_as2 [NN];
__device__ float  g_ad2 [NN];
__device__ int    g_counts [NN];
__device__ int    g_rowstart[NN + 1];
__device__ int    g_cursor [NN];
__device__ int    g_csrsrc [NET];
__device__ float  g_pooled [NG * HID];
__device__ float  g_gcnt   [NG];
__device__ int    g_idx64;

#define SCH 1024
#define SNB ((NN + SCH - 1) / SCH)     // 20
__device__ int g_bsum[SNB];

// ------------------------- helpers -------------------------
__device__ __forceinline__ float warpSum(float v) {
    #pragma unroll
    for (int o = 16; o > 0; o >>= 1) v += __shfl_xor_sync(0xffffffffu, v, o);
    return v;
}
__device__ __forceinline__ float lrelu(float x) { return x > 0.f ? x : NEG * x; }
__device__ __forceinline__ int clampi(int v, int hi) {
    return v < 0 ? 0 : (v >= hi ? hi - 1 : v);
}
__device__ __forceinline__ int idx_at(const void* p, int i) {
    if (g_idx64) return (int)((const long long*)p)[i];
    return ((const int*)p)[i];
}
__device__ __forceinline__ unsigned f2tf32(float f) {   // RNA rounding — required:
    unsigned r;                                         // RZ truncation gave 2.1e-3 (R10)
    asm("cvt.rna.tf32.f32 %0, %1;" : "=r"(r) : "f"(f));
    return r;
}
__device__ __forceinline__ void mma_tf32(float* c, unsigned a0, unsigned a1,
                                         unsigned a2, unsigned a3,
                                         unsigned b0, unsigned b1) {
    asm("mma.sync.aligned.m16n8k8.row.col.f32.tf32.tf32.f32 "
        "{%0,%1,%2,%3}, {%4,%5,%6,%7}, {%8,%9}, {%0,%1,%2,%3};"
        : "+f"(c[0]), "+f"(c[1]), "+f"(c[2]), "+f"(c[3])
        : "r"(a0), "r"(a1), "r"(a2), "r"(a3), "r"(b0), "r"(b1));
}
__device__ __forceinline__ void cp16(void* dst, const void* src, int sz) {
    unsigned d = (unsigned)__cvta_generic_to_shared(dst);
    asm volatile("cp.async.ca.shared.global [%0], [%1], 16, %2;"
                 :: "r"(d), "l"(src), "r"(sz));
}
__device__ __forceinline__ void cp_commit() { asm volatile("cp.async.commit_group;"); }
template<int N> __device__ __forceinline__ void cp_wait() {
    asm volatile("cp.async.wait_group %0;" :: "n"(N));
}

// ------------------------- zero scratch + dtype detection -------------------------
// Grid MUST cover NN (g_counts) — stale counts accumulate across graph replays
// otherwise and corrupt the CSR (R8 bug).
__global__ void zero_kernel(const int* __restrict__ ei32) {
    int i = blockIdx.x * blockDim.x + threadIdx.x;
    if (i == 0) {
        int allzero = 1;
        #pragma unroll 1
        for (int k = 1; k < 128; k += 2)
            if (ei32[k] != 0) { allzero = 0; break; }
        g_idx64 = allzero;
    }
    if (i < NN) g_counts[i] = 0;
    if (i < NG * HID) g_pooled[i] = 0.f;
    if (i < NG) g_gcnt[i] = 0.f;
}

// ------------------------- CSR build -------------------------
__global__ void hist_kernel(const void* __restrict__ ei) {
    int i = blockIdx.x * blockDim.x + threadIdx.x;
    if (i >= NET) return;
    int dst = (i < NE) ? clampi(idx_at(ei, NE + i), NN) : (i - NE);
    atomicAdd(&g_counts[dst], 1);
}

__global__ void scan1_kernel() {
    __shared__ int sbuf[SCH];
    int b = blockIdx.x, t = threadIdx.x;
    int i = b * SCH + t;
    int v = (i < NN) ? g_counts[i] : 0;
    sbuf[t] = v;
    __syncthreads();
    #pragma unroll
    for (int off = 1; off < SCH; off <<= 1) {
        int x = (t >= off) ? sbuf[t - off] : 0;
        __syncthreads();
        sbuf[t] += x;
        __syncthreads();
    }
    if (i < NN) g_rowstart[i + 1] = sbuf[t];
    if (t == SCH - 1) g_bsum[b] = sbuf[t];
}

// fixup: add block offsets (each thread sums <=20 block sums), derive cursor
__global__ void scan3_kernel() {
    int i = blockIdx.x * blockDim.x + threadIdx.x;
    if (i >= NN) return;
    if (i == 0) g_rowstart[0] = 0;
    int blk = i >> 10;
    int off = 0;
    for (int b = 0; b < blk; b++) off += g_bsum[b];
    int fin = g_rowstart[i + 1] + off;
    g_rowstart[i + 1] = fin;
    g_cursor[i] = fin - g_counts[i];
}

__global__ void scatter_kernel(const void* __restrict__ ei) {
    int i = blockIdx.x * blockDim.x + threadIdx.x;
    if (i >= NET) return;
    int src, dst;
    if (i < NE) {
        src = clampi(idx_at(ei, i), NN);
        dst = clampi(idx_at(ei, NE + i), NN);
    } else {
        src = dst = i - NE;
    }
    int pos = atomicAdd(&g_cursor[dst], 1);
    g_csrsrc[pos] = src;
}

// ------------------------- TF32 GEMM 128x128, 2-stage cp.async, fused att ------
// C[M,N] = A[M,K] @ B[K,N] row-major -> half Ch. N%128==0, K%16==0, M guarded.
// Block covers exactly one head's columns (N block = 128 = HID), so the fused
// attention dot (asOut/adOut) uses plain stores (no atomics, no pre-zero).
#define GBM 128
#define GBN 128
#define GBK 16
#define APAD 4   // As stride 20 floats -> conflict-free
#define BPAD 8   // Bs stride 136 floats -> conflict-free

__device__ __forceinline__ void tf32_gemm_fused(const float* __restrict__ A,
                                                const float* __restrict__ B,
                                                __half* __restrict__ Ch,
                                                int M, int N, int K,
                                                const float* __restrict__ attS,
                                                const float* __restrict__ attD,
                                                float* __restrict__ asOut,
                                                float* __restrict__ adOut,
                                                int heads) {
    __shared__ float As[2][GBM][GBK + APAD];
    __shared__ float Bs[2][GBK][GBN + BPAD];
    __shared__ float s_eas[2][GBM];
    __shared__ float s_ead[2][GBM];

    int tid  = threadIdx.x;
    int lane = tid & 31;
    int warp = tid >> 5;
    int wm = warp & 3;          // M offset wm*32
    int wn = warp >> 2;         // N offset wn*64
    int rowBase = blockIdx.y * GBM;
    int colBase = blockIdx.x * GBN;
    int q  = lane & 3;
    int r0 = lane >> 2;

    int aRow = tid >> 2;            // 0..63
    int aCol = (tid & 3) * 4;       // 0,4,8,12
    int bRow = tid >> 5;            // 0..7
    int bCol = (tid & 31) * 4;      // 0..124

    int nIter = K / GBK;
    float acc[2][8][4] = {};

    // prologue: tile 0
    {
        #pragma unroll
        for (int i = 0; i < 2; i++) {
            int row = aRow + 64 * i;
            int gr = rowBase + row;
            const float* src = (gr < M) ? &A[(long long)gr * K + aCol] : A;
            cp16(&As[0][row][aCol], src, (gr < M) ? 16 : 0);
        }
        #pragma unroll
        for (int i = 0; i < 2; i++) {
            int row = bRow + 8 * i;
            cp16(&Bs[0][row][bCol], &B[(long long)row * N + colBase + bCol], 16);
        }
        cp_commit();
    }

    for (int it = 0; it < nIter; it++) {
        int cur = it & 1;
        cp_wait<0>();
        __syncthreads();                    // tile `it` ready in buf cur

        if (it + 1 < nIter) {               // prefetch next into other buf
            int k0 = (it + 1) * GBK;
            int st = cur ^ 1;
            #pragma unroll
            for (int i = 0; i < 2; i++) {
                int row = aRow + 64 * i;
                int gr = rowBase + row;
                const float* src = (gr < M) ? &A[(long long)gr * K + k0 + aCol] : A;
                cp16(&As[st][row][aCol], src, (gr < M) ? 16 : 0);
            }
            #pragma unroll
            for (int i = 0; i < 2; i++) {
                int row = bRow + 8 * i;
                cp16(&Bs[st][row][bCol], &B[(long long)(k0 + row) * N + colBase + bCol], 16);
            }
            cp_commit();
        }

        #pragma unroll
        for (int kk = 0; kk < 2; kk++) {
            int kb = kk * 8;
            unsigned a[2][4], b[8][2];
            #pragma unroll
            for (int mf = 0; mf < 2; mf++) {
                int mrow = wm * 32 + mf * 16 + r0;
                a[mf][0] = f2tf32(As[cur][mrow    ][kb + q    ]);
                a[mf][1] = f2tf32(As[cur][mrow + 8][kb + q    ]);
                a[mf][2] = f2tf32(As[cur][mrow    ][kb + q + 4]);
                a[mf][3] = f2tf32(As[cur][mrow + 8][kb + q + 4]);
            }
            #pragma unroll
            for (int nf = 0; nf < 8; nf++) {
                int ncol = wn * 64 + nf * 8 + r0;
                b[nf][0] = f2tf32(Bs[cur][kb + q    ][ncol]);
                b[nf][1] = f2tf32(Bs[cur][kb + q + 4][ncol]);
            }
            #pragma unroll
            for (int mf = 0; mf < 2; mf++)
                #pragma unroll
                for (int nf = 0; nf < 8; nf++)
                    mma_tf32(acc[mf][nf], a[mf][0], a[mf][1], a[mf][2], a[mf][3],
                             b[nf][0], b[nf][1]);
        }
        __syncthreads();                    // compute done before next prefetch reuses buf
    }

    // ---- fused epilogue: attention partial dots (no atomics) + fp16 store ----
    int hd = colBase / HID;
    float attSv[16], attDv[16];
    #pragma unroll
    for (int nf = 0; nf < 8; nf++) {
        int gc = colBase + wn * 64 + nf * 8 + 2 * q;
        attSv[nf*2]   = attS[gc];   attSv[nf*2+1] = attS[gc+1];
        attDv[nf*2]   = attD[gc];   attDv[nf*2+1] = attD[gc+1];
    }
    #pragma unroll
    for (int mf = 0; mf < 2; mf++) {
        int rT = wm * 32 + mf * 16 + r0;    // row within block
        float psT = 0.f, pdT = 0.f, psB = 0.f, pdB = 0.f;
        #pragma unroll
        for (int nf = 0; nf < 8; nf++) {
            psT += acc[mf][nf][0]*attSv[nf*2] + acc[mf][nf][1]*attSv[nf*2+1];
            pdT += acc[mf][nf][0]*attDv[nf*2] + acc[mf][nf][1]*attDv[nf*2+1];
            psB += acc[mf][nf][2]*attSv[nf*2] + acc[mf][nf][3]*attSv[nf*2+1];
            pdB += acc[mf][nf][2]*attDv[nf*2] + acc[mf][nf][3]*attDv[nf*2+1];
        }
        #pragma unroll
        for (int o = 1; o < 4; o <<= 1) {
            psT += __shfl_xor_sync(0xffffffffu, psT, o);
            pdT += __shfl_xor_sync(0xffffffffu, pdT, o);
            psB += __shfl_xor_sync(0xffffffffu, psB, o);
            pdB += __shfl_xor_sync(0xffffffffu, pdB, o);
        }
        if (q == 0) {
            s_eas[wn][rT]     = psT;  s_ead[wn][rT]     = pdT;
            s_eas[wn][rT + 8] = psB;  s_ead[wn][rT + 8] = pdB;
        }
        #pragma unroll
        for (int nf = 0; nf < 8; nf++) {
            int gc = colBase + wn * 64 + nf * 8 + 2 * q;
            int gr0 = rowBase + rT;
            if (gr0 < M)
                *(__half2*)&Ch[(long long)gr0 * N + gc] =
                    __floats2half2_rn(acc[mf][nf][0], acc[mf][nf][1]);
            if (gr0 + 8 < M)
                *(__half2*)&Ch[(long long)(gr0 + 8) * N + gc] =
                    __floats2half2_rn(acc[mf][nf][2], acc[mf][nf][3]);
        }
    }
    __syncthreads();
    if (tid < GBM) {
        int gr = rowBase + tid;
        if (gr < M) {
            asOut[gr * heads + hd] = s_eas[0][tid] + s_eas[1][tid];
            adOut[gr * heads + hd] = s_ead[0][tid] + s_ead[1][tid];
        }
    }
}

__global__ __launch_bounds__(256) void gemm1_kernel(const float* __restrict__ x,
                                                    const float* __restrict__ W1,
                                                    const float* __restrict__ as1,
                                                    const float* __restrict__ ad1) {
    tf32_gemm_fused(x, W1, g_h1h, NN, F1, IN_CH, as1, ad1, g_as1, g_ad1, HEADS);
}

__global__ __launch_bounds__(256) void gemm2_kernel(const float* __restrict__ W2,
                                                    const float* __restrict__ as2,
                                                    const float* __restrict__ ad2) {
    tf32_gemm_fused(g_h1b, W2, g_h2h, NN, HID, F1, as2, ad2, g_as2, g_ad2, 1);
}

// ------------------------- layer-1 aggregation: single pass, vectorized ------
__global__ __launch_bounds__(128) void agg1_kernel(const float* __restrict__ b1) {
    int n = blockIdx.x, t = threadIdx.x;
    int beg = g_rowstart[n], end = g_rowstart[n + 1];
    int head = t >> 5;

    float4 adst = *(const float4*)&g_ad1[n * HEADS];

    __shared__ float4 s_w[32];
    __shared__ int    ssrc[32];
    __shared__ float  s_finv[HEADS];

    float acc0 = 0.f, acc1 = 0.f, acc2 = 0.f, acc3 = 0.f;
    float4 dsum = make_float4(0.f, 0.f, 0.f, 0.f);

    for (int base = beg; base < end; base += 32) {
        int cnt = min(32, end - base);
        __syncthreads();
        if (t < cnt) {
            int s = g_csrsrc[base + t];
            ssrc[t] = s;
            float4 a = *(const float4*)&g_as1[s * HEADS];
            float4 w;
            w.x = __expf(lrelu(a.x + adst.x));
            w.y = __expf(lrelu(a.y + adst.y));
            w.z = __expf(lrelu(a.z + adst.z));
            w.w = __expf(lrelu(a.w + adst.w));
            s_w[t] = w;
            dsum.x += w.x; dsum.y += w.y; dsum.z += w.z; dsum.w += w.w;
        }
        __syncthreads();
        for (int qq = 0; qq < cnt; qq++) {
            int s = ssrc[qq];
            float wq = ((const float*)&s_w[qq])[head];
            uint2 hv = *(const uint2*)&g_h1h[(long long)s * F1 + 4 * t];
            float2 f01 = __half22float2(*(__half2*)&hv.x);
            float2 f23 = __half22float2(*(__half2*)&hv.y);
            acc0 += wq * f01.x; acc1 += wq * f01.y;
            acc2 += wq * f23.x; acc3 += wq * f23.y;
        }
    }
    dsum.x = warpSum(dsum.x); dsum.y = warpSum(dsum.y);
    dsum.z = warpSum(dsum.z); dsum.w = warpSum(dsum.w);
    if (t == 0) {
        s_finv[0] = 1.f / dsum.x; s_finv[1] = 1.f / dsum.y;
        s_finv[2] = 1.f / dsum.z; s_finv[3] = 1.f / dsum.w;
    }
    __syncthreads();
    float fin = s_finv[head];
    float4 bv = *(const float4*)&b1[4 * t];
    float4 o;
    o.x = fmaxf(acc0 * fin + bv.x, 0.f);
    o.y = fmaxf(acc1 * fin + bv.y, 0.f);
    o.z = fmaxf(acc2 * fin + bv.z, 0.f);
    o.w = fmaxf(acc3 * fin + bv.w, 0.f);
    *(float4*)&g_h1b[(long long)n * F1 + 4 * t] = o;
}

// ------------------------- layer-2 aggregation: single pass + fused pool ------
__global__ __launch_bounds__(128) void agg2_kernel(const float* __restrict__ b2,
                                                   const void* __restrict__ batch) {
    int n = blockIdx.x, t = threadIdx.x;
    int beg = g_rowstart[n], end = g_rowstart[n + 1];
    float adst = g_ad2[n];
    int grp = t >> 6;
    int c   = t & 63;

    __shared__ float s_w[64];
    __shared__ int   ssrc[64];
    __shared__ float s_accB[HID];
    __shared__ float wr2[2];

    float2 acc = make_float2(0.f, 0.f);
    float dsum = 0.f;

    for (int base = beg; base < end; base += 64) {
        int cnt = min(64, end - base);
        __syncthreads();
        if (t < cnt) {
            int s = g_csrsrc[base + t];
            ssrc[t] = s;
            float w = __expf(lrelu(g_as2[s] + adst));
            s_w[t] = w;
            dsum += w;
        }
        __syncthreads();
        for (int qq = grp; qq < cnt; qq += 2) {
            int s = ssrc[qq];
            float w = s_w[qq];
            float2 f = __half22float2(*(const __half2*)&g_h2h[(long long)s * HID + 2 * c]);
            acc.x += w * f.x; acc.y += w * f.y;
        }
    }
    dsum = warpSum(dsum);
    if ((t & 31) == 0 && t < 64) wr2[t >> 5] = dsum;
    if (grp == 1) { s_accB[2 * c] = acc.x; s_accB[2 * c + 1] = acc.y; }
    __syncthreads();
    if (grp == 0) {
        float di = 1.f / (wr2[0] + wr2[1]);
        float o0 = (acc.x + s_accB[2 * c])     * di + b2[2 * c];
        float o1 = (acc.y + s_accB[2 * c + 1]) * di + b2[2 * c + 1];
        int g = clampi(idx_at(batch, n), NG);
        atomicAdd(&g_pooled[g * HID + 2 * c],     o0);
        atomicAdd(&g_pooled[g * HID + 2 * c + 1], o1);
        if (t == 0) atomicAdd(&g_gcnt[g], 1.0f);
    }
}

// ------------------------- MLP head -------------------------
__global__ void mlp_kernel(const float* __restrict__ Wm1, const float* __restrict__ bm1,
                           const float* __restrict__ Wm2, const float* __restrict__ bm2,
                           float* __restrict__ out) {
    int g = blockIdx.x, t = threadIdx.x;
    __shared__ float p[HID], z[HID];
    float c = fmaxf(g_gcnt[g], 1.0f);
    p[t] = g_pooled[g * HID + t] / c;
    __syncthreads();
    float a = bm1[t];
    #pragma unroll 8
    for (int k = 0; k < HID; k++) a += p[k] * Wm1[k * HID + t];
    z[t] = a > 0.f ? a : 0.f;
    __syncthreads();
    if (t < OC) {
        float o = bm2[t];
        #pragma unroll 8
        for (int k = 0; k < HID; k++) o += z[k] * Wm2[k * OC + t];
        out[g * OC + t] = o;
    }
}

// ------------------------- launch -------------------------
extern "C" void kernel_launch(void* const* d_in, const int* in_sizes, int n_in,
                              void* d_out, int out_size) {
    const float* x    = (const float*)d_in[0];
    const void*  ei   = d_in[1];
    const void*  bat  = d_in[2];
    const float* W1   = (const float*)d_in[3];
    const float* as1  = (const float*)d_in[4];
    const float* ad1  = (const float*)d_in[5];
    const float* b1   = (const float*)d_in[6];
    const float* W2   = (const float*)d_in[7];
    const float* as2  = (const float*)d_in[8];
    const float* ad2  = (const float*)d_in[9];
    const float* b2   = (const float*)d_in[10];
    const float* Wm1  = (const float*)d_in[11];
    const float* bm1  = (const float*)d_in[12];
    const float* Wm2  = (const float*)d_in[13];
    const float* bm2  = (const float*)d_in[14];
    float* out = (float*)d_out;

    zero_kernel<<<(NN + 255) / 256, 256>>>((const int*)ei);   // must cover NN!
    hist_kernel<<<(NET + 255) / 256, 256>>>(ei);
    scan1_kernel<<<SNB, SCH>>>();
    scan3_kernel<<<(NN + 255) / 256, 256>>>();
    scatter_kernel<<<(NET + 255) / 256, 256>>>(ei);

    // Layer 1
    {
        dim3 grid(F1 / GBN, (NN + GBM - 1) / GBM);
        gemm1_kernel<<<grid, 256>>>(x, W1, as1, ad1);
    }
    agg1_kernel<<<NN, 128>>>(b1);

    // Layer 2
    {
        dim3 grid(HID / GBN, (NN + GBM - 1) / GBM);
        gemm2_kernel<<<grid, 256>>>(W2, as2, ad2);
    }
    agg2_kernel<<<NN, 128>>>(b2, bat);

    mlp_kernel<<<NG, HID>>>(Wm1, bm1, Wm2, bm2, out);
}

// round 13
// speedup vs baseline: 2.7590x; 1.0614x over previous
#include <cuda_runtime.h>
#include <cuda_bf16.h>
#include <cuda_fp16.h>

// Problem constants
#define NN      20000        // nodes
#define NE      320000       // raw edges
#define NET     340000       // edges + self loops
#define IN_CH   256
#define HID     128
#define HEADS   4
#define F1      (HEADS*HID)  // 512
#define NG      128          // graphs
#define OC      16
#define NEG     0.2f

// ------------------------- device scratch -------------------------
__device__ __half g_h1h [NN * F1];     // x @ W1 (fp16 for gather)
__device__ float  g_h1b [NN * F1];     // relu(agg1 + b1)  (GEMM2 input, fp32)
__device__ __half g_h2h [NN * HID];    // h1b @ W2 (fp16 for gather)
__device__ float  g_as1 [NN * HEADS];
__device__ float  g_ad1 [NN * HEADS];
__device__ float  g_as2 [NN];
__device__ float  g_ad2 [NN];
__device__ int    g_counts [NN];
__device__ int    g_rowstart[NN + 1];
__device__ int    g_cursor [NN];
__device__ int    g_csrsrc [NET];
__device__ float  g_pooled [NG * HID];
__device__ float  g_gcnt   [NG];
__device__ int    g_idx64;

#define SCH 1024
#define SNB ((NN + SCH - 1) / SCH)     // 20
__device__ int g_bsum[SNB];

// ------------------------- helpers -------------------------
__device__ __forceinline__ float warpSum(float v) {
    #pragma unroll
    for (int o = 16; o > 0; o >>= 1) v += __shfl_xor_sync(0xffffffffu, v, o);
    return v;
}
__device__ __forceinline__ float lrelu(float x) { return x > 0.f ? x : NEG * x; }
__device__ __forceinline__ int clampi(int v, int hi) {
    return v < 0 ? 0 : (v >= hi ? hi - 1 : v);
}
__device__ __forceinline__ int idx_at(const void* p, int i) {
    if (g_idx64) return (int)((const long long*)p)[i];
    return ((const int*)p)[i];
}
__device__ __forceinline__ unsigned f2tf32(float f) {   // RNA rounding — required:
    unsigned r;                                         // RZ truncation gave 2.1e-3 (R10)
    asm("cvt.rna.tf32.f32 %0, %1;" : "=r"(r) : "f"(f));
    return r;
}
__device__ __forceinline__ void mma_tf32(float* c, unsigned a0, unsigned a1,
                                         unsigned a2, unsigned a3,
                                         unsigned b0, unsigned b1) {
    asm("mma.sync.aligned.m16n8k8.row.col.f32.tf32.tf32.f32 "
        "{%0,%1,%2,%3}, {%4,%5,%6,%7}, {%8,%9}, {%0,%1,%2,%3};"
        : "+f"(c[0]), "+f"(c[1]), "+f"(c[2]), "+f"(c[3])
        : "r"(a0), "r"(a1), "r"(a2), "r"(a3), "r"(b0), "r"(b1));
}
__device__ __forceinline__ void cp16(void* dst, const void* src, int sz) {
    unsigned d = (unsigned)__cvta_generic_to_shared(dst);
    asm volatile("cp.async.ca.shared.global [%0], [%1], 16, %2;"
                 :: "r"(d), "l"(src), "r"(sz));
}
__device__ __forceinline__ void cp_commit() { asm volatile("cp.async.commit_group;"); }
template<int N> __device__ __forceinline__ void cp_wait() {
    asm volatile("cp.async.wait_group %0;" :: "n"(N));
}

// ------------------------- zero scratch + dtype detection -------------------------
// Grid MUST cover NN (g_counts) — stale counts accumulate across graph replays
// otherwise and corrupt the CSR (R8 bug).
__global__ void zero_kernel(const int* __restrict__ ei32) {
    int i = blockIdx.x * blockDim.x + threadIdx.x;
    if (i == 0) {
        int allzero = 1;
        #pragma unroll 1
        for (int k = 1; k < 128; k += 2)
            if (ei32[k] != 0) { allzero = 0; break; }
        g_idx64 = allzero;
    }
    if (i < NN) g_counts[i] = 0;
    if (i < NG * HID) g_pooled[i] = 0.f;
    if (i < NG) g_gcnt[i] = 0.f;
}

// ------------------------- CSR build -------------------------
__global__ void hist_kernel(const void* __restrict__ ei) {
    int i = blockIdx.x * blockDim.x + threadIdx.x;
    if (i >= NET) return;
    int dst = (i < NE) ? clampi(idx_at(ei, NE + i), NN) : (i - NE);
    atomicAdd(&g_counts[dst], 1);
}

__global__ void scan1_kernel() {
    __shared__ int sbuf[SCH];
    int b = blockIdx.x, t = threadIdx.x;
    int i = b * SCH + t;
    int v = (i < NN) ? g_counts[i] : 0;
    sbuf[t] = v;
    __syncthreads();
    #pragma unroll
    for (int off = 1; off < SCH; off <<= 1) {
        int x = (t >= off) ? sbuf[t - off] : 0;
        __syncthreads();
        sbuf[t] += x;
        __syncthreads();
    }
    if (i < NN) g_rowstart[i + 1] = sbuf[t];
    if (t == SCH - 1) g_bsum[b] = sbuf[t];
}

// fixup: add block offsets (each thread sums <=20 block sums), derive cursor
__global__ void scan3_kernel() {
    int i = blockIdx.x * blockDim.x + threadIdx.x;
    if (i >= NN) return;
    if (i == 0) g_rowstart[0] = 0;
    int blk = i >> 10;
    int off = 0;
    for (int b = 0; b < blk; b++) off += g_bsum[b];
    int fin = g_rowstart[i + 1] + off;
    g_rowstart[i + 1] = fin;
    g_cursor[i] = fin - g_counts[i];
}

__global__ void scatter_kernel(const void* __restrict__ ei) {
    int i = blockIdx.x * blockDim.x + threadIdx.x;
    if (i >= NET) return;
    int src, dst;
    if (i < NE) {
        src = clampi(idx_at(ei, i), NN);
        dst = clampi(idx_at(ei, NE + i), NN);
    } else {
        src = dst = i - NE;
    }
    int pos = atomicAdd(&g_cursor[dst], 1);
    g_csrsrc[pos] = src;
}

// ------------------------- TF32 GEMM 128x128, 2-stage cp.async, fused att ------
// C[M,N] = A[M,K] @ B[K,N] row-major -> half Ch. N%128==0, K%16==0, M guarded.
// Block covers exactly one head's columns (N block = 128 = HID), so the fused
// attention dot (asOut/adOut) uses plain stores (no atomics, no pre-zero).
#define GBM 128
#define GBN 128
#define GBK 16
#define APAD 4   // As stride 20 floats -> conflict-free
#define BPAD 8   // Bs stride 136 floats -> conflict-free

__device__ __forceinline__ void tf32_gemm_fused(const float* __restrict__ A,
                                                const float* __restrict__ B,
                                                __half* __restrict__ Ch,
                                                int M, int N, int K,
                                                const float* __restrict__ attS,
                                                const float* __restrict__ attD,
                                                float* __restrict__ asOut,
                                                float* __restrict__ adOut,
                                                int heads) {
    __shared__ float As[2][GBM][GBK + APAD];
    __shared__ float Bs[2][GBK][GBN + BPAD];
    __shared__ float s_eas[2][GBM];
    __shared__ float s_ead[2][GBM];

    int tid  = threadIdx.x;
    int lane = tid & 31;
    int warp = tid >> 5;
    int wm = warp & 3;          // M offset wm*32
    int wn = warp >> 2;         // N offset wn*64
    int rowBase = blockIdx.y * GBM;
    int colBase = blockIdx.x * GBN;
    int q  = lane & 3;
    int r0 = lane >> 2;

    int aRow = tid >> 2;            // 0..63
    int aCol = (tid & 3) * 4;       // 0,4,8,12
    int bRow = tid >> 5;            // 0..7
    int bCol = (tid & 31) * 4;      // 0..124

    int nIter = K / GBK;
    float acc[2][8][4] = {};

    // prologue: tile 0
    {
        #pragma unroll
        for (int i = 0; i < 2; i++) {
            int row = aRow + 64 * i;
            int gr = rowBase + row;
            const float* src = (gr < M) ? &A[(long long)gr * K + aCol] : A;
            cp16(&As[0][row][aCol], src, (gr < M) ? 16 : 0);
        }
        #pragma unroll
        for (int i = 0; i < 2; i++) {
            int row = bRow + 8 * i;
            cp16(&Bs[0][row][bCol], &B[(long long)row * N + colBase + bCol], 16);
        }
        cp_commit();
    }

    for (int it = 0; it < nIter; it++) {
        int cur = it & 1;
        cp_wait<0>();
        __syncthreads();                    // tile `it` ready in buf cur

        if (it + 1 < nIter) {               // prefetch next into other buf
            int k0 = (it + 1) * GBK;
            int st = cur ^ 1;
            #pragma unroll
            for (int i = 0; i < 2; i++) {
                int row = aRow + 64 * i;
                int gr = rowBase + row;
                const float* src = (gr < M) ? &A[(long long)gr * K + k0 + aCol] : A;
                cp16(&As[st][row][aCol], src, (gr < M) ? 16 : 0);
            }
            #pragma unroll
            for (int i = 0; i < 2; i++) {
                int row = bRow + 8 * i;
                cp16(&Bs[st][row][bCol], &B[(long long)(k0 + row) * N + colBase + bCol], 16);
            }
            cp_commit();
        }

        #pragma unroll
        for (int kk = 0; kk < 2; kk++) {
            int kb = kk * 8;
            unsigned a[2][4], b[8][2];
            #pragma unroll
            for (int mf = 0; mf < 2; mf++) {
                int mrow = wm * 32 + mf * 16 + r0;
                a[mf][0] = f2tf32(As[cur][mrow    ][kb + q    ]);
                a[mf][1] = f2tf32(As[cur][mrow + 8][kb + q    ]);
                a[mf][2] = f2tf32(As[cur][mrow    ][kb + q + 4]);
                a[mf][3] = f2tf32(As[cur][mrow + 8][kb + q + 4]);
            }
            #pragma unroll
            for (int nf = 0; nf < 8; nf++) {
                int ncol = wn * 64 + nf * 8 + r0;
                b[nf][0] = f2tf32(Bs[cur][kb + q    ][ncol]);
                b[nf][1] = f2tf32(Bs[cur][kb + q + 4][ncol]);
            }
            #pragma unroll
            for (int mf = 0; mf < 2; mf++)
                #pragma unroll
                for (int nf = 0; nf < 8; nf++)
                    mma_tf32(acc[mf][nf], a[mf][0], a[mf][1], a[mf][2], a[mf][3],
                             b[nf][0], b[nf][1]);
        }
        __syncthreads();                    // compute done before next prefetch reuses buf
    }

    // ---- fused epilogue: attention partial dots (no atomics) + fp16 store ----
    int hd = colBase / HID;
    float attSv[16], attDv[16];
    #pragma unroll
    for (int nf = 0; nf < 8; nf++) {
        int gc = colBase + wn * 64 + nf * 8 + 2 * q;
        attSv[nf*2]   = attS[gc];   attSv[nf*2+1] = attS[gc+1];
        attDv[nf*2]   = attD[gc];   attDv[nf*2+1] = attD[gc+1];
    }
    #pragma unroll
    for (int mf = 0; mf < 2; mf++) {
        int rT = wm * 32 + mf * 16 + r0;    // row within block
        float psT = 0.f, pdT = 0.f, psB = 0.f, pdB = 0.f;
        #pragma unroll
        for (int nf = 0; nf < 8; nf++) {
            psT += acc[mf][nf][0]*attSv[nf*2] + acc[mf][nf][1]*attSv[nf*2+1];
            pdT += acc[mf][nf][0]*attDv[nf*2] + acc[mf][nf][1]*attDv[nf*2+1];
            psB += acc[mf][nf][2]*attSv[nf*2] + acc[mf][nf][3]*attSv[nf*2+1];
            pdB += acc[mf][nf][2]*attDv[nf*2] + acc[mf][nf][3]*attDv[nf*2+1];
        }
        #pragma unroll
        for (int o = 1; o < 4; o <<= 1) {
            psT += __shfl_xor_sync(0xffffffffu, psT, o);
            pdT += __shfl_xor_sync(0xffffffffu, pdT, o);
            psB += __shfl_xor_sync(0xffffffffu, psB, o);
            pdB += __shfl_xor_sync(0xffffffffu, pdB, o);
        }
        if (q == 0) {
            s_eas[wn][rT]     = psT;  s_ead[wn][rT]     = pdT;
            s_eas[wn][rT + 8] = psB;  s_ead[wn][rT + 8] = pdB;
        }
        #pragma unroll
        for (int nf = 0; nf < 8; nf++) {
            int gc = colBase + wn * 64 + nf * 8 + 2 * q;
            int gr0 = rowBase + rT;
            if (gr0 < M)
                *(__half2*)&Ch[(long long)gr0 * N + gc] =
                    __floats2half2_rn(acc[mf][nf][0], acc[mf][nf][1]);
            if (gr0 + 8 < M)
                *(__half2*)&Ch[(long long)(gr0 + 8) * N + gc] =
                    __floats2half2_rn(acc[mf][nf][2], acc[mf][nf][3]);
        }
    }
    __syncthreads();
    if (tid < GBM) {
        int gr = rowBase + tid;
        if (gr < M) {
            asOut[gr * heads + hd] = s_eas[0][tid] + s_eas[1][tid];
            adOut[gr * heads + hd] = s_ead[0][tid] + s_ead[1][tid];
        }
    }
}

__global__ __launch_bounds__(256) void gemm1_kernel(const float* __restrict__ x,
                                                    const float* __restrict__ W1,
                                                    const float* __restrict__ as1,
                                                    const float* __restrict__ ad1) {
    tf32_gemm_fused(x, W1, g_h1h, NN, F1, IN_CH, as1, ad1, g_as1, g_ad1, HEADS);
}

__global__ __launch_bounds__(256) void gemm2_kernel(const float* __restrict__ W2,
                                                    const float* __restrict__ as2,
                                                    const float* __restrict__ ad2) {
    tf32_gemm_fused(g_h1b, W2, g_h2h, NN, HID, F1, as2, ad2, g_as2, g_ad2, 1);
}

// ------------------------- layer-1 aggregation: single pass, vectorized ------
__global__ __launch_bounds__(128) void agg1_kernel(const float* __restrict__ b1) {
    int n = blockIdx.x, t = threadIdx.x;
    int beg = g_rowstart[n], end = g_rowstart[n + 1];
    int head = t >> 5;

    float4 adst = *(const float4*)&g_ad1[n * HEADS];

    __shared__ float4 s_w[32];
    __shared__ int    ssrc[32];
    __shared__ float  s_finv[HEADS];

    float acc0 = 0.f, acc1 = 0.f, acc2 = 0.f, acc3 = 0.f;
    float4 dsum = make_float4(0.f, 0.f, 0.f, 0.f);

    for (int base = beg; base < end; base += 32) {
        int cnt = min(32, end - base);
        __syncthreads();
        if (t < cnt) {
            int s = g_csrsrc[base + t];
            ssrc[t] = s;
            float4 a = *(const float4*)&g_as1[s * HEADS];
            float4 w;
            w.x = __expf(lrelu(a.x + adst.x));
            w.y = __expf(lrelu(a.y + adst.y));
            w.z = __expf(lrelu(a.z + adst.z));
            w.w = __expf(lrelu(a.w + adst.w));
            s_w[t] = w;
            dsum.x += w.x; dsum.y += w.y; dsum.z += w.z; dsum.w += w.w;
        }
        __syncthreads();
        for (int qq = 0; qq < cnt; qq++) {
            int s = ssrc[qq];
            float wq = ((const float*)&s_w[qq])[head];
            uint2 hv = *(const uint2*)&g_h1h[(long long)s * F1 + 4 * t];
            float2 f01 = __half22float2(*(__half2*)&hv.x);
            float2 f23 = __half22float2(*(__half2*)&hv.y);
            acc0 += wq * f01.x; acc1 += wq * f01.y;
            acc2 += wq * f23.x; acc3 += wq * f23.y;
        }
    }
    dsum.x = warpSum(dsum.x); dsum.y = warpSum(dsum.y);
    dsum.z = warpSum(dsum.z); dsum.w = warpSum(dsum.w);
    if (t == 0) {
        s_finv[0] = 1.f / dsum.x; s_finv[1] = 1.f / dsum.y;
        s_finv[2] = 1.f / dsum.z; s_finv[3] = 1.f / dsum.w;
    }
    __syncthreads();
    float fin = s_finv[head];
    float4 bv = *(const float4*)&b1[4 * t];
    float4 o;
    o.x = fmaxf(acc0 * fin + bv.x, 0.f);
    o.y = fmaxf(acc1 * fin + bv.y, 0.f);
    o.z = fmaxf(acc2 * fin + bv.z, 0.f);
    o.w = fmaxf(acc3 * fin + bv.w, 0.f);
    *(float4*)&g_h1b[(long long)n * F1 + 4 * t] = o;
}

// ------------------------- layer-2 aggregation: single pass + fused pool ------
__global__ __launch_bounds__(128) void agg2_kernel(const float* __restrict__ b2,
                                                   const void* __restrict__ batch) {
    int n = blockIdx.x, t = threadIdx.x;
    int beg = g_rowstart[n], end = g_rowstart[n + 1];
    float adst = g_ad2[n];
    int grp = t >> 6;
    int c   = t & 63;

    __shared__ float s_w[64];
    __shared__ int   ssrc[64];
    __shared__ float s_accB[HID];
    __shared__ float wr2[2];

    float2 acc = make_float2(0.f, 0.f);
    float dsum = 0.f;

    for (int base = beg; base < end; base += 64) {
        int cnt = min(64, end - base);
        __syncthreads();
        if (t < cnt) {
            int s = g_csrsrc[base + t];
            ssrc[t] = s;
            float w = __expf(lrelu(g_as2[s] + adst));
            s_w[t] = w;
            dsum += w;
        }
        __syncthreads();
        for (int qq = grp; qq < cnt; qq += 2) {
            int s = ssrc[qq];
            float w = s_w[qq];
            float2 f = __half22float2(*(const __half2*)&g_h2h[(long long)s * HID + 2 * c]);
            acc.x += w * f.x; acc.y += w * f.y;
        }
    }
    dsum = warpSum(dsum);
    if ((t & 31) == 0 && t < 64) wr2[t >> 5] = dsum;
    if (grp == 1) { s_accB[2 * c] = acc.x; s_accB[2 * c + 1] = acc.y; }
    __syncthreads();
    if (grp == 0) {
        float di = 1.f / (wr2[0] + wr2[1]);
        float o0 = (acc.x + s_accB[2 * c])     * di + b2[2 * c];
        float o1 = (acc.y + s_accB[2 * c + 1]) * di + b2[2 * c + 1];
        int g = clampi(idx_at(batch, n), NG);
        atomicAdd(&g_pooled[g * HID + 2 * c],     o0);
        atomicAdd(&g_pooled[g * HID + 2 * c + 1], o1);
        if (t == 0) atomicAdd(&g_gcnt[g], 1.0f);
    }
}

// ------------------------- MLP head -------------------------
__global__ void mlp_kernel(const float* __restrict__ Wm1, const float* __restrict__ bm1,
                           const float* __restrict__ Wm2, const float* __restrict__ bm2,
                           float* __restrict__ out) {
    int g = blockIdx.x, t = threadIdx.x;
    __shared__ float p[HID], z[HID];
    float c = fmaxf(g_gcnt[g], 1.0f);
    p[t] = g_pooled[g * HID + t] / c;
    __syncthreads();
    float a = bm1[t];
    #pragma unroll 8
    for (int k = 0; k < HID; k++) a += p[k] * Wm1[k * HID + t];
    z[t] = a > 0.f ? a : 0.f;
    __syncthreads();
    if (t < OC) {
        float o = bm2[t];
        #pragma unroll 8
        for (int k = 0; k < HID; k++) o += z[k] * Wm2[k * OC + t];
        out[g * OC + t] = o;
    }
}

// ------------------------- launch -------------------------
// DAG: CSR chain (needs ei only) runs concurrently with gemm1 (needs x, W1).
// Fork/join via events — graph-capturable, no syncs, no device allocations.
// Stream/events are created fresh each call and intentionally NOT destroyed
// (kernel_launch runs only a handful of times; replays use the captured graph;
// destroying a stream that participates in an active capture would break it).
extern "C" void kernel_launch(void* const* d_in, const int* in_sizes, int n_in,
                              void* d_out, int out_size) {
    const float* x    = (const float*)d_in[0];
    const void*  ei   = d_in[1];
    const void*  bat  = d_in[2];
    const float* W1   = (const float*)d_in[3];
    const float* as1  = (const float*)d_in[4];
    const float* ad1  = (const float*)d_in[5];
    const float* b1   = (const float*)d_in[6];
    const float* W2   = (const float*)d_in[7];
    const float* as2  = (const float*)d_in[8];
    const float* ad2  = (const float*)d_in[9];
    const float* b2   = (const float*)d_in[10];
    const float* Wm1  = (const float*)d_in[11];
    const float* bm1  = (const float*)d_in[12];
    const float* Wm2  = (const float*)d_in[13];
    const float* bm2  = (const float*)d_in[14];
    float* out = (float*)d_out;

    cudaStream_t s2;
    cudaStreamCreateWithFlags(&s2, cudaStreamNonBlocking);
    cudaEvent_t eFork, eGemm1;
    cudaEventCreateWithFlags(&eFork,  cudaEventDisableTiming);
    cudaEventCreateWithFlags(&eGemm1, cudaEventDisableTiming);

    // fork: branch B (gemm1) on s2
    cudaEventRecord(eFork, 0);
    cudaStreamWaitEvent(s2, eFork, 0);
    {
        dim3 grid(F1 / GBN, (NN + GBM - 1) / GBM);
        gemm1_kernel<<<grid, 256, 0, s2>>>(x, W1, as1, ad1);
    }
    cudaEventRecord(eGemm1, s2);

    // branch A (CSR build) on the main stream
    zero_kernel<<<(NN + 255) / 256, 256>>>((const int*)ei);   // must cover NN!
    hist_kernel<<<(NET + 255) / 256, 256>>>(ei);
    scan1_kernel<<<SNB, SCH>>>();
    scan3_kernel<<<(NN + 255) / 256, 256>>>();
    scatter_kernel<<<(NET + 255) / 256, 256>>>(ei);

    // join: agg1 needs both CSR and gemm1
    cudaStreamWaitEvent(0, eGemm1, 0);
    agg1_kernel<<<NN, 128>>>(b1);

    // Layer 2 (sequential tail)
    {
        dim3 grid(HID / GBN, (NN + GBM - 1) / GBM);
        gemm2_kernel<<<grid, 256>>>(W2, as2, ad2);
    }
    agg2_kernel<<<NN, 128>>>(b2, bat);

    mlp_kernel<<<NG, HID>>>(Wm1, bm1, Wm2, bm2, out);
}

// round 14
// speedup vs baseline: 3.3130x; 1.2008x over previous
#include <cuda_runtime.h>
#include <cuda_bf16.h>
#include <cuda_fp16.h>

// Problem constants
#define NN      20000        // nodes
#define NE      320000       // raw edges
#define NET     340000       // edges + self loops
#define IN_CH   256
#define HID     128
#define HEADS   4
#define F1      (HEADS*HID)  // 512
#define NG      128          // graphs
#define OC      16
#define NEG     0.2f

// ------------------------- device scratch -------------------------
__device__ __align__(16) __half g_xh  [NN * IN_CH];   // x in fp16
__device__ __align__(16) __half g_w1t [F1 * IN_CH];   // W1^T [n][k] fp16
__device__ __align__(16) __half g_w2t [HID * F1];     // W2^T [n][k] fp16
__device__ __align__(16) __half g_h1h [NN * F1];      // x @ W1 (fp16)
__device__ __align__(16) __half g_h1bh[NN * F1];      // relu(agg1 + b1) (fp16)
__device__ __align__(16) __half g_h2h [NN * HID];     // h1b @ W2 (fp16)
__device__ float  g_as1 [NN * HEADS];
__device__ float  g_ad1 [NN * HEADS];
__device__ float  g_as2 [NN];
__device__ float  g_ad2 [NN];
__device__ int    g_counts [NN];
__device__ int    g_rowstart[NN + 1];
__device__ int    g_cursor [NN];
__device__ int    g_csrsrc [NET];
__device__ float  g_pooled [NG * HID];
__device__ float  g_gcnt   [NG];
__device__ int    g_idx64;

#define SCH 1024
#define SNB ((NN + SCH - 1) / SCH)     // 20
__device__ int g_bsum[SNB];

// ------------------------- helpers -------------------------
__device__ __forceinline__ float warpSum(float v) {
    #pragma unroll
    for (int o = 16; o > 0; o >>= 1) v += __shfl_xor_sync(0xffffffffu, v, o);
    return v;
}
__device__ __forceinline__ float lrelu(float x) { return x > 0.f ? x : NEG * x; }
__device__ __forceinline__ int clampi(int v, int hi) {
    return v < 0 ? 0 : (v >= hi ? hi - 1 : v);
}
__device__ __forceinline__ int idx_at(const void* p, int i) {
    if (g_idx64) return (int)((const long long*)p)[i];
    return ((const int*)p)[i];
}
// fp16 MMA: same 10-bit mantissa as tf32 (RNA input convert happens in
// the cvt kernels via __float2half_rn), fp32 accumulate. 2048 MACs/instr.
__device__ __forceinline__ void mma_f16(float* c, unsigned a0, unsigned a1,
                                        unsigned a2, unsigned a3,
                                        unsigned b0, unsigned b1) {
    asm("mma.sync.aligned.m16n8k16.row.col.f32.f16.f16.f32 "
        "{%0,%1,%2,%3}, {%4,%5,%6,%7}, {%8,%9}, {%0,%1,%2,%3};"
        : "+f"(c[0]), "+f"(c[1]), "+f"(c[2]), "+f"(c[3])
        : "r"(a0), "r"(a1), "r"(a2), "r"(a3), "r"(b0), "r"(b1));
}
__device__ __forceinline__ void cp16(void* dst, const void* src, int sz) {
    unsigned d = (unsigned)__cvta_generic_to_shared(dst);
    asm volatile("cp.async.ca.shared.global [%0], [%1], 16, %2;"
                 :: "r"(d), "l"(src), "r"(sz));
}
__device__ __forceinline__ void cp_commit() { asm volatile("cp.async.commit_group;"); }
template<int N> __device__ __forceinline__ void cp_wait() {
    asm volatile("cp.async.wait_group %0;" :: "n"(N));
}

// ------------------------- conversion kernels -------------------------
__global__ void cvt_x_kernel(const float* __restrict__ x) {
    int i4 = blockIdx.x * blockDim.x + threadIdx.x;
    if (i4 >= NN * IN_CH / 4) return;
    float4 v = ((const float4*)x)[i4];
    __half2 h01 = __floats2half2_rn(v.x, v.y);
    __half2 h23 = __floats2half2_rn(v.z, v.w);
    ((uint2*)g_xh)[i4] = make_uint2(*(unsigned*)&h01, *(unsigned*)&h23);
}
__global__ void cvt_w1_kernel(const float* __restrict__ W1) {   // [k][n] -> [n][k]
    int i = blockIdx.x * blockDim.x + threadIdx.x;
    if (i >= F1 * IN_CH) return;
    int n = i / IN_CH, k = i % IN_CH;
    g_w1t[i] = __float2half_rn(W1[k * F1 + n]);
}
__global__ void cvt_w2_kernel(const float* __restrict__ W2) {   // [k][n] -> [n][k]
    int i = blockIdx.x * blockDim.x + threadIdx.x;
    if (i >= HID * F1) return;
    int n = i / F1, k = i % F1;
    g_w2t[i] = __float2half_rn(W2[k * HID + n]);
}

// ------------------------- zero scratch + dtype detection -------------------------
// Grid MUST cover NN (g_counts) — stale counts accumulate across graph replays
// otherwise and corrupt the CSR (R8 bug).
__global__ void zero_kernel(const int* __restrict__ ei32) {
    int i = blockIdx.x * blockDim.x + threadIdx.x;
    if (i == 0) {
        int allzero = 1;
        #pragma unroll 1
        for (int k = 1; k < 128; k += 2)
            if (ei32[k] != 0) { allzero = 0; break; }
        g_idx64 = allzero;
    }
    if (i < NN) g_counts[i] = 0;
    if (i < NG * HID) g_pooled[i] = 0.f;
    if (i < NG) g_gcnt[i] = 0.f;
}

// ------------------------- CSR build -------------------------
__global__ void hist_kernel(const void* __restrict__ ei) {
    int i = blockIdx.x * blockDim.x + threadIdx.x;
    if (i >= NET) return;
    int dst = (i < NE) ? clampi(idx_at(ei, NE + i), NN) : (i - NE);
    atomicAdd(&g_counts[dst], 1);
}

__global__ void scan1_kernel() {
    __shared__ int sbuf[SCH];
    int b = blockIdx.x, t = threadIdx.x;
    int i = b * SCH + t;
    int v = (i < NN) ? g_counts[i] : 0;
    sbuf[t] = v;
    __syncthreads();
    #pragma unroll
    for (int off = 1; off < SCH; off <<= 1) {
        int x = (t >= off) ? sbuf[t - off] : 0;
        __syncthreads();
        sbuf[t] += x;
        __syncthreads();
    }
    if (i < NN) g_rowstart[i + 1] = sbuf[t];
    if (t == SCH - 1) g_bsum[b] = sbuf[t];
}

__global__ void scan3_kernel() {
    int i = blockIdx.x * blockDim.x + threadIdx.x;
    if (i >= NN) return;
    if (i == 0) g_rowstart[0] = 0;
    int blk = i >> 10;
    int off = 0;
    for (int b = 0; b < blk; b++) off += g_bsum[b];
    int fin = g_rowstart[i + 1] + off;
    g_rowstart[i + 1] = fin;
    g_cursor[i] = fin - g_counts[i];
}

__global__ void scatter_kernel(const void* __restrict__ ei) {
    int i = blockIdx.x * blockDim.x + threadIdx.x;
    if (i >= NET) return;
    int src, dst;
    if (i < NE) {
        src = clampi(idx_at(ei, i), NN);
        dst = clampi(idx_at(ei, NE + i), NN);
    } else {
        src = dst = i - NE;
    }
    int pos = atomicAdd(&g_cursor[dst], 1);
    g_csrsrc[pos] = src;
}

// ------------------------- FP16 GEMM 128x128, 2-stage cp.async, fused att ------
// C[M,N] = A[M,K] @ Bt[N,K]^T (A row-major [m][k] half, Bt pre-transposed
// [n][k] half) -> half Ch, fp32 accum. N%128==0, K%32==0, M guarded.
// Block covers one head's columns, so fused att dots use plain stores.
#define GBM 128
#define GBN 128
#define HK  32   // k halves per stage
#define HPAD 8   // stride 40 halves = 80B: rows 0..7 -> banks {0,20,8,28,16,4,24,12} — conflict-free

__device__ __forceinline__ void f16_gemm_fused(const __half* __restrict__ A,
                                               const __half* __restrict__ Bt,
                                               __half* __restrict__ Ch,
                                               int M, int N, int K,
                                               const float* __restrict__ attS,
                                               const float* __restrict__ attD,
                                               float* __restrict__ asOut,
                                               float* __restrict__ adOut,
                                               int heads) {
    __shared__ __half As[2][GBM][HK + HPAD];
    __shared__ __half Bs[2][GBN][HK + HPAD];
    __shared__ float s_eas[2][GBM];
    __shared__ float s_ead[2][GBM];

    int tid  = threadIdx.x;
    int lane = tid & 31;
    int warp = tid >> 5;
    int wm = warp & 3;          // M offset wm*32
    int wn = warp >> 2;         // N offset wn*64
    int rowBase = blockIdx.y * GBM;
    int colBase = blockIdx.x * GBN;
    int q  = lane & 3;
    int r0 = lane >> 2;

    int ldRow = tid >> 2;           // 0..63
    int ldCol = (tid & 3) * 8;      // 0,8,16,24 halves (16B)

    int nIter = K / HK;
    float acc[2][8][4] = {};

    // prologue: stage 0
    {
        #pragma unroll
        for (int i = 0; i < 2; i++) {
            int row = ldRow + 64 * i;
            int gr = rowBase + row;
            const __half* src = (gr < M) ? &A[(long long)gr * K + ldCol] : A;
            cp16(&As[0][row][ldCol], src, (gr < M) ? 16 : 0);
            cp16(&Bs[0][row][ldCol], &Bt[(long long)(colBase + row) * K + ldCol], 16);
        }
        cp_commit();
    }

    for (int it = 0; it < nIter; it++) {
        int cur = it & 1;
        cp_wait<0>();
        __syncthreads();                    // stage `it` ready

        if (it + 1 < nIter) {
            int k0 = (it + 1) * HK;
            int st = cur ^ 1;
            #pragma unroll
            for (int i = 0; i < 2; i++) {
                int row = ldRow + 64 * i;
                int gr = rowBase + row;
                const __half* src = (gr < M) ? &A[(long long)gr * K + k0 + ldCol] : A;
                cp16(&As[st][row][ldCol], src, (gr < M) ? 16 : 0);
                cp16(&Bs[st][row][ldCol], &Bt[(long long)(colBase + row) * K + k0 + ldCol], 16);
            }
            cp_commit();
        }

        #pragma unroll
        for (int kk = 0; kk < 2; kk++) {
            int kb = kk * 16;
            unsigned a[2][4], b[8][2];
            #pragma unroll
            for (int mf = 0; mf < 2; mf++) {
                int mrow = wm * 32 + mf * 16 + r0;
                a[mf][0] = *(const unsigned*)&As[cur][mrow    ][kb + 2*q    ];
                a[mf][1] = *(const unsigned*)&As[cur][mrow + 8][kb + 2*q    ];
                a[mf][2] = *(const unsigned*)&As[cur][mrow    ][kb + 2*q + 8];
                a[mf][3] = *(const unsigned*)&As[cur][mrow + 8][kb + 2*q + 8];
            }
            #pragma unroll
            for (int nf = 0; nf < 8; nf++) {
                int ncol = wn * 64 + nf * 8 + r0;
                b[nf][0] = *(const unsigned*)&Bs[cur][ncol][kb + 2*q    ];
                b[nf][1] = *(const unsigned*)&Bs[cur][ncol][kb + 2*q + 8];
            }
            #pragma unroll
            for (int mf = 0; mf < 2; mf++)
                #pragma unroll
                for (int nf = 0; nf < 8; nf++)
                    mma_f16(acc[mf][nf], a[mf][0], a[mf][1], a[mf][2], a[mf][3],
                            b[nf][0], b[nf][1]);
        }
        __syncthreads();
    }

    // ---- fused epilogue: attention partial dots (no atomics) + fp16 store ----
    int hd = colBase / HID;
    float attSv[16], attDv[16];
    #pragma unroll
    for (int nf = 0; nf < 8; nf++) {
        int gc = colBase + wn * 64 + nf * 8 + 2 * q;
        attSv[nf*2]   = attS[gc];   attSv[nf*2+1] = attS[gc+1];
        attDv[nf*2]   = attD[gc];   attDv[nf*2+1] = attD[gc+1];
    }
    #pragma unroll
    for (int mf = 0; mf < 2; mf++) {
        int rT = wm * 32 + mf * 16 + r0;
        float psT = 0.f, pdT = 0.f, psB = 0.f, pdB = 0.f;
        #pragma unroll
        for (int nf = 0; nf < 8; nf++) {
            psT += acc[mf][nf][0]*attSv[nf*2] + acc[mf][nf][1]*attSv[nf*2+1];
            pdT += acc[mf][nf][0]*attDv[nf*2] + acc[mf][nf][1]*attDv[nf*2+1];
            psB += acc[mf][nf][2]*attSv[nf*2] + acc[mf][nf][3]*attSv[nf*2+1];
            pdB += acc[mf][nf][2]*attDv[nf*2] + acc[mf][nf][3]*attDv[nf*2+1];
        }
        #pragma unroll
        for (int o = 1; o < 4; o <<= 1) {
            psT += __shfl_xor_sync(0xffffffffu, psT, o);
            pdT += __shfl_xor_sync(0xffffffffu, pdT, o);
            psB += __shfl_xor_sync(0xffffffffu, psB, o);
            pdB += __shfl_xor_sync(0xffffffffu, pdB, o);
        }
        if (q == 0) {
            s_eas[wn][rT]     = psT;  s_ead[wn][rT]     = pdT;
            s_eas[wn][rT + 8] = psB;  s_ead[wn][rT + 8] = pdB;
        }
        #pragma unroll
        for (int nf = 0; nf < 8; nf++) {
            int gc = colBase + wn * 64 + nf * 8 + 2 * q;
            int gr0 = rowBase + rT;
            if (gr0 < M)
                *(__half2*)&Ch[(long long)gr0 * N + gc] =
                    __floats2half2_rn(acc[mf][nf][0], acc[mf][nf][1]);
            if (gr0 + 8 < M)
                *(__half2*)&Ch[(long long)(gr0 + 8) * N + gc] =
                    __floats2half2_rn(acc[mf][nf][2], acc[mf][nf][3]);
        }
    }
    __syncthreads();
    if (tid < GBM) {
        int gr = rowBase + tid;
        if (gr < M) {
            asOut[gr * heads + hd] = s_eas[0][tid] + s_eas[1][tid];
            adOut[gr * heads + hd] = s_ead[0][tid] + s_ead[1][tid];
        }
    }
}

__global__ __launch_bounds__(256) void gemm1_kernel(const float* __restrict__ as1,
                                                    const float* __restrict__ ad1) {
    f16_gemm_fused(g_xh, g_w1t, g_h1h, NN, F1, IN_CH, as1, ad1, g_as1, g_ad1, HEADS);
}

__global__ __launch_bounds__(256) void gemm2_kernel(const float* __restrict__ as2,
                                                    const float* __restrict__ ad2) {
    f16_gemm_fused(g_h1bh, g_w2t, g_h2h, NN, HID, F1, as2, ad2, g_as2, g_ad2, 1);
}

// ------------------------- layer-1 aggregation: single pass, vectorized ------
__global__ __launch_bounds__(128) void agg1_kernel(const float* __restrict__ b1) {
    int n = blockIdx.x, t = threadIdx.x;
    int beg = g_rowstart[n], end = g_rowstart[n + 1];
    int head = t >> 5;

    float4 adst = *(const float4*)&g_ad1[n * HEADS];

    __shared__ float4 s_w[32];
    __shared__ int    ssrc[32];
    __shared__ float  s_finv[HEADS];

    float acc0 = 0.f, acc1 = 0.f, acc2 = 0.f, acc3 = 0.f;
    float4 dsum = make_float4(0.f, 0.f, 0.f, 0.f);

    for (int base = beg; base < end; base += 32) {
        int cnt = min(32, end - base);
        __syncthreads();
        if (t < cnt) {
            int s = g_csrsrc[base + t];
            ssrc[t] = s;
            float4 a = *(const float4*)&g_as1[s * HEADS];
            float4 w;
            w.x = __expf(lrelu(a.x + adst.x));
            w.y = __expf(lrelu(a.y + adst.y));
            w.z = __expf(lrelu(a.z + adst.z));
            w.w = __expf(lrelu(a.w + adst.w));
            s_w[t] = w;
            dsum.x += w.x; dsum.y += w.y; dsum.z += w.z; dsum.w += w.w;
        }
        __syncthreads();
        for (int qq = 0; qq < cnt; qq++) {
            int s = ssrc[qq];
            float wq = ((const float*)&s_w[qq])[head];
            uint2 hv = *(const uint2*)&g_h1h[(long long)s * F1 + 4 * t];
            float2 f01 = __half22float2(*(__half2*)&hv.x);
            float2 f23 = __half22float2(*(__half2*)&hv.y);
            acc0 += wq * f01.x; acc1 += wq * f01.y;
            acc2 += wq * f23.x; acc3 += wq * f23.y;
        }
    }
    dsum.x = warpSum(dsum.x); dsum.y = warpSum(dsum.y);
    dsum.z = warpSum(dsum.z); dsum.w = warpSum(dsum.w);
    if (t == 0) {
        s_finv[0] = 1.f / dsum.x; s_finv[1] = 1.f / dsum.y;
        s_finv[2] = 1.f / dsum.z; s_finv[3] = 1.f / dsum.w;
    }
    __syncthreads();
    float fin = s_finv[head];
    float4 bv = *(const float4*)&b1[4 * t];
    __half2 h01 = __floats2half2_rn(fmaxf(acc0 * fin + bv.x, 0.f),
                                    fmaxf(acc1 * fin + bv.y, 0.f));
    __half2 h23 = __floats2half2_rn(fmaxf(acc2 * fin + bv.z, 0.f),
                                    fmaxf(acc3 * fin + bv.w, 0.f));
    *(uint2*)&g_h1bh[(long long)n * F1 + 4 * t] =
        make_uint2(*(unsigned*)&h01, *(unsigned*)&h23);
}

// ------------------------- layer-2 aggregation: single pass + fused pool ------
__global__ __launch_bounds__(128) void agg2_kernel(const float* __restrict__ b2,
                                                   const void* __restrict__ batch) {
    int n = blockIdx.x, t = threadIdx.x;
    int beg = g_rowstart[n], end = g_rowstart[n + 1];
    float adst = g_ad2[n];
    int grp = t >> 6;
    int c   = t & 63;

    __shared__ float s_w[64];
    __shared__ int   ssrc[64];
    __shared__ float s_accB[HID];
    __shared__ float wr2[2];

    float2 acc = make_float2(0.f, 0.f);
    float dsum = 0.f;

    for (int base = beg; base < end; base += 64) {
        int cnt = min(64, end - base);
        __syncthreads();
        if (t < cnt) {
            int s = g_csrsrc[base + t];
            ssrc[t] = s;
            float w = __expf(lrelu(g_as2[s] + adst));
            s_w[t] = w;
            dsum += w;
        }
        __syncthreads();
        for (int qq = grp; qq < cnt; qq += 2) {
            int s = ssrc[qq];
            float w = s_w[qq];
            float2 f = __half22float2(*(const __half2*)&g_h2h[(long long)s * HID + 2 * c]);
            acc.x += w * f.x; acc.y += w * f.y;
        }
    }
    dsum = warpSum(dsum);
    if ((t & 31) == 0 && t < 64) wr2[t >> 5] = dsum;
    if (grp == 1) { s_accB[2 * c] = acc.x; s_accB[2 * c + 1] = acc.y; }
    __syncthreads();
    if (grp == 0) {
        float di = 1.f / (wr2[0] + wr2[1]);
        float o0 = (acc.x + s_accB[2 * c])     * di + b2[2 * c];
        float o1 = (acc.y + s_accB[2 * c + 1]) * di + b2[2 * c + 1];
        int g = clampi(idx_at(batch, n), NG);
        atomicAdd(&g_pooled[g * HID + 2 * c],     o0);
        atomicAdd(&g_pooled[g * HID + 2 * c + 1], o1);
        if (t == 0) atomicAdd(&g_gcnt[g], 1.0f);
    }
}

// ------------------------- MLP head -------------------------
__global__ void mlp_kernel(const float* __restrict__ Wm1, const float* __restrict__ bm1,
                           const float* __restrict__ Wm2, const float* __restrict__ bm2,
                           float* __restrict__ out) {
    int g = blockIdx.x, t = threadIdx.x;
    __shared__ float p[HID], z[HID];
    float c = fmaxf(g_gcnt[g], 1.0f);
    p[t] = g_pooled[g * HID + t] / c;
    __syncthreads();
    float a = bm1[t];
    #pragma unroll 8
    for (int k = 0; k < HID; k++) a += p[k] * Wm1[k * HID + t];
    z[t] = a > 0.f ? a : 0.f;
    __syncthreads();
    if (t < OC) {
        float o = bm2[t];
        #pragma unroll 8
        for (int k = 0; k < HID; k++) o += z[k] * Wm2[k * OC + t];
        out[g * OC + t] = o;
    }
}

// ------------------------- launch -------------------------
// DAG: CSR chain (ei only) runs concurrently with cvt_x/cvt_w1 -> gemm1 on s2.
// Stream/events created fresh each call, never destroyed (graph capture safe;
// kernel_launch itself runs only a handful of times).
extern "C" void kernel_launch(void* const* d_in, const int* in_sizes, int n_in,
                              void* d_out, int out_size) {
    const float* x    = (const float*)d_in[0];
    const void*  ei   = d_in[1];
    const void*  bat  = d_in[2];
    const float* W1   = (const float*)d_in[3];
    const float* as1  = (const float*)d_in[4];
    const float* ad1  = (const float*)d_in[5];
    const float* b1   = (const float*)d_in[6];
    const float* W2   = (const float*)d_in[7];
    const float* as2  = (const float*)d_in[8];
    const float* ad2  = (const float*)d_in[9];
    const float* b2   = (const float*)d_in[10];
    const float* Wm1  = (const float*)d_in[11];
    const float* bm1  = (const float*)d_in[12];
    const float* Wm2  = (const float*)d_in[13];
    const float* bm2  = (const float*)d_in[14];
    float* out = (float*)d_out;

    cudaStream_t s2;
    cudaStreamCreateWithFlags(&s2, cudaStreamNonBlocking);
    cudaEvent_t eFork, eGemm1;
    cudaEventCreateWithFlags(&eFork,  cudaEventDisableTiming);
    cudaEventCreateWithFlags(&eGemm1, cudaEventDisableTiming);

    // fork: branch B on s2 — convert inputs to fp16, then gemm1
    cudaEventRecord(eFork, 0);
    cudaStreamWaitEvent(s2, eFork, 0);
    cvt_x_kernel <<<(NN * IN_CH / 4 + 255) / 256, 256, 0, s2>>>(x);
    cvt_w1_kernel<<<(F1 * IN_CH + 255) / 256, 256, 0, s2>>>(W1);
    {
        dim3 grid(F1 / GBN, (NN + GBM - 1) / GBM);
        gemm1_kernel<<<grid, 256, 0, s2>>>(as1, ad1);
    }
    cudaEventRecord(eGemm1, s2);

    // branch A (main stream): W2 convert + CSR build
    cvt_w2_kernel<<<(HID * F1 + 255) / 256, 256>>>(W2);
    zero_kernel<<<(NN + 255) / 256, 256>>>((const int*)ei);   // must cover NN!
    hist_kernel<<<(NET + 255) / 256, 256>>>(ei);
    scan1_kernel<<<SNB, SCH>>>();
    scan3_kernel<<<(NN + 255) / 256, 256>>>();
    scatter_kernel<<<(NET + 255) / 256, 256>>>(ei);

    // join: agg1 needs CSR + gemm1
    cudaStreamWaitEvent(0, eGemm1, 0);
    agg1_kernel<<<NN, 128>>>(b1);

    // Layer 2
    {
        dim3 grid(HID / GBN, (NN + GBM - 1) / GBM);
        gemm2_kernel<<<grid, 256>>>(as2, ad2);
    }
    agg2_kernel<<<NN, 128>>>(b2, bat);

    mlp_kernel<<<NG, HID>>>(Wm1, bm1, Wm2, bm2, out);
}

// round 15
// speedup vs baseline: 3.3895x; 1.0231x over previous
#include <cuda_runtime.h>
#include <cuda_bf16.h>
#include <cuda_fp16.h>

// Problem constants
#define NN      20000        // nodes
#define NE      320000       // raw edges
#define NET     340000       // edges + self loops
#define IN_CH   256
#define HID     128
#define HEADS   4
#define F1      (HEADS*HID)  // 512
#define NG      128          // graphs
#define OC      16
#define NEG     0.2f

// node split for layer1->layer2 pipelining (multiple of 128)
#define NLO     10112
#define RB_ALL  ((NN + 127) / 128)          // 157 row blocks
#define RB_LO   (NLO / 128)                 // 79
#define RB_HI   (RB_ALL - RB_LO)            // 78

// ------------------------- device scratch -------------------------
__device__ __align__(16) __half g_xh  [NN * IN_CH];   // x in fp16
__device__ __align__(16) __half g_w1t [F1 * IN_CH];   // W1^T [n][k] fp16
__device__ __align__(16) __half g_w2t [HID * F1];     // W2^T [n][k] fp16
__device__ __align__(16) __half g_h1h [NN * F1];      // x @ W1 (fp16)
__device__ __align__(16) __half g_h1bh[NN * F1];      // relu(agg1 + b1) (fp16)
__device__ __align__(16) __half g_h2h [NN * HID];     // h1b @ W2 (fp16)
__device__ float  g_as1 [NN * HEADS];
__device__ float  g_ad1 [NN * HEADS];
__device__ float  g_as2 [NN];
__device__ float  g_ad2 [NN];
__device__ int    g_counts [NN];
__device__ int    g_rowstart[NN + 1];
__device__ int    g_cursor [NN];
__device__ int    g_csrsrc [NET];
__device__ float  g_pooled [NG * HID];
__device__ float  g_gcnt   [NG];
__device__ int    g_idx64;

#define SCH 1024
#define SNB ((NN + SCH - 1) / SCH)     // 20
__device__ int g_bsum[SNB];

// ------------------------- helpers -------------------------
__device__ __forceinline__ float warpSum(float v) {
    #pragma unroll
    for (int o = 16; o > 0; o >>= 1) v += __shfl_xor_sync(0xffffffffu, v, o);
    return v;
}
__device__ __forceinline__ float lrelu(float x) { return x > 0.f ? x : NEG * x; }
__device__ __forceinline__ int clampi(int v, int hi) {
    return v < 0 ? 0 : (v >= hi ? hi - 1 : v);
}
__device__ __forceinline__ int idx_at(const void* p, int i) {
    if (g_idx64) return (int)((const long long*)p)[i];
    return ((const int*)p)[i];
}
__device__ __forceinline__ void mma_f16(float* c, unsigned a0, unsigned a1,
                                        unsigned a2, unsigned a3,
                                        unsigned b0, unsigned b1) {
    asm("mma.sync.aligned.m16n8k16.row.col.f32.f16.f16.f32 "
        "{%0,%1,%2,%3}, {%4,%5,%6,%7}, {%8,%9}, {%0,%1,%2,%3};"
        : "+f"(c[0]), "+f"(c[1]), "+f"(c[2]), "+f"(c[3])
        : "r"(a0), "r"(a1), "r"(a2), "r"(a3), "r"(b0), "r"(b1));
}
__device__ __forceinline__ void cp16(void* dst, const void* src, int sz) {
    unsigned d = (unsigned)__cvta_generic_to_shared(dst);
    asm volatile("cp.async.ca.shared.global [%0], [%1], 16, %2;"
                 :: "r"(d), "l"(src), "r"(sz));
}
__device__ __forceinline__ void cp_commit() { asm volatile("cp.async.commit_group;"); }
template<int N> __device__ __forceinline__ void cp_wait() {
    asm volatile("cp.async.wait_group %0;" :: "n"(N));
}

// ------------------------- conversion kernels -------------------------
__global__ void cvt_x_kernel(const float* __restrict__ x) {
    int i4 = blockIdx.x * blockDim.x + threadIdx.x;
    if (i4 >= NN * IN_CH / 4) return;
    float4 v = ((const float4*)x)[i4];
    __half2 h01 = __floats2half2_rn(v.x, v.y);
    __half2 h23 = __floats2half2_rn(v.z, v.w);
    ((uint2*)g_xh)[i4] = make_uint2(*(unsigned*)&h01, *(unsigned*)&h23);
}
__global__ void cvt_w1_kernel(const float* __restrict__ W1) {   // [k][n] -> [n][k]
    int i = blockIdx.x * blockDim.x + threadIdx.x;
    if (i >= F1 * IN_CH) return;
    int n = i / IN_CH, k = i % IN_CH;
    g_w1t[i] = __float2half_rn(W1[k * F1 + n]);
}
__global__ void cvt_w2_kernel(const float* __restrict__ W2) {   // [k][n] -> [n][k]
    int i = blockIdx.x * blockDim.x + threadIdx.x;
    if (i >= HID * F1) return;
    int n = i / F1, k = i % F1;
    g_w2t[i] = __float2half_rn(W2[k * HID + n]);
}

// ------------------------- zero scratch + dtype detection -------------------------
// Grid MUST cover NN (g_counts) — stale counts accumulate across graph replays
// otherwise and corrupt the CSR (R8 bug).
__global__ void zero_kernel(const int* __restrict__ ei32) {
    int i = blockIdx.x * blockDim.x + threadIdx.x;
    if (i == 0) {
        int allzero = 1;
        #pragma unroll 1
        for (int k = 1; k < 128; k += 2)
            if (ei32[k] != 0) { allzero = 0; break; }
        g_idx64 = allzero;
    }
    if (i < NN) g_counts[i] = 0;
    if (i < NG * HID) g_pooled[i] = 0.f;
    if (i < NG) g_gcnt[i] = 0.f;
}

// ------------------------- CSR build -------------------------
__global__ void hist_kernel(const void* __restrict__ ei) {
    int i = blockIdx.x * blockDim.x + threadIdx.x;
    if (i >= NET) return;
    int dst = (i < NE) ? clampi(idx_at(ei, NE + i), NN) : (i - NE);
    atomicAdd(&g_counts[dst], 1);
}

__global__ void scan1_kernel() {
    __shared__ int sbuf[SCH];
    int b = blockIdx.x, t = threadIdx.x;
    int i = b * SCH + t;
    int v = (i < NN) ? g_counts[i] : 0;
    sbuf[t] = v;
    __syncthreads();
    #pragma unroll
    for (int off = 1; off < SCH; off <<= 1) {
        int x = (t >= off) ? sbuf[t - off] : 0;
        __syncthreads();
        sbuf[t] += x;
        __syncthreads();
    }
    if (i < NN) g_rowstart[i + 1] = sbuf[t];
    if (t == SCH - 1) g_bsum[b] = sbuf[t];
}

__global__ void scan3_kernel() {
    int i = blockIdx.x * blockDim.x + threadIdx.x;
    if (i >= NN) return;
    if (i == 0) g_rowstart[0] = 0;
    int blk = i >> 10;
    int off = 0;
    for (int b = 0; b < blk; b++) off += g_bsum[b];
    int fin = g_rowstart[i + 1] + off;
    g_rowstart[i + 1] = fin;
    g_cursor[i] = fin - g_counts[i];
}

__global__ void scatter_kernel(const void* __restrict__ ei) {
    int i = blockIdx.x * blockDim.x + threadIdx.x;
    if (i >= NET) return;
    int src, dst;
    if (i < NE) {
        src = clampi(idx_at(ei, i), NN);
        dst = clampi(idx_at(ei, NE + i), NN);
    } else {
        src = dst = i - NE;
    }
    int pos = atomicAdd(&g_cursor[dst], 1);
    g_csrsrc[pos] = src;
}

// ------------------------- FP16 GEMM 128x128, 2-stage cp.async, fused att ------
// C[M,N] = A[M,K] @ Bt[N,K]^T, fp32 accum -> half. rowBlockOff shifts the M
// block range so halves of the row space can run on different streams.
#define GBM 128
#define GBN 128
#define HK  32
#define HPAD 8

__device__ __forceinline__ void f16_gemm_fused(const __half* __restrict__ A,
                                               const __half* __restrict__ Bt,
                                               __half* __restrict__ Ch,
                                               int M, int N, int K,
                                               const float* __restrict__ attS,
                                               const float* __restrict__ attD,
                                               float* __restrict__ asOut,
                                               float* __restrict__ adOut,
                                               int heads, int rowBlockOff) {
    __shared__ __half As[2][GBM][HK + HPAD];
    __shared__ __half Bs[2][GBN][HK + HPAD];
    __shared__ float s_eas[2][GBM];
    __shared__ float s_ead[2][GBM];

    int tid  = threadIdx.x;
    int lane = tid & 31;
    int warp = tid >> 5;
    int wm = warp & 3;
    int wn = warp >> 2;
    int rowBase = (blockIdx.y + rowBlockOff) * GBM;
    int colBase = blockIdx.x * GBN;
    int q  = lane & 3;
    int r0 = lane >> 2;

    int ldRow = tid >> 2;
    int ldCol = (tid & 3) * 8;

    int nIter = K / HK;
    float acc[2][8][4] = {};

    {
        #pragma unroll
        for (int i = 0; i < 2; i++) {
            int row = ldRow + 64 * i;
            int gr = rowBase + row;
            const __half* src = (gr < M) ? &A[(long long)gr * K + ldCol] : A;
            cp16(&As[0][row][ldCol], src, (gr < M) ? 16 : 0);
            cp16(&Bs[0][row][ldCol], &Bt[(long long)(colBase + row) * K + ldCol], 16);
        }
        cp_commit();
    }

    for (int it = 0; it < nIter; it++) {
        int cur = it & 1;
        cp_wait<0>();
        __syncthreads();

        if (it + 1 < nIter) {
            int k0 = (it + 1) * HK;
            int st = cur ^ 1;
            #pragma unroll
            for (int i = 0; i < 2; i++) {
                int row = ldRow + 64 * i;
                int gr = rowBase + row;
                const __half* src = (gr < M) ? &A[(long long)gr * K + k0 + ldCol] : A;
                cp16(&As[st][row][ldCol], src, (gr < M) ? 16 : 0);
                cp16(&Bs[st][row][ldCol], &Bt[(long long)(colBase + row) * K + k0 + ldCol], 16);
            }
            cp_commit();
        }

        #pragma unroll
        for (int kk = 0; kk < 2; kk++) {
            int kb = kk * 16;
            unsigned a[2][4], b[8][2];
            #pragma unroll
            for (int mf = 0; mf < 2; mf++) {
                int mrow = wm * 32 + mf * 16 + r0;
                a[mf][0] = *(const unsigned*)&As[cur][mrow    ][kb + 2*q    ];
                a[mf][1] = *(const unsigned*)&As[cur][mrow + 8][kb + 2*q    ];
                a[mf][2] = *(const unsigned*)&As[cur][mrow    ][kb + 2*q + 8];
                a[mf][3] = *(const unsigned*)&As[cur][mrow + 8][kb + 2*q + 8];
            }
            #pragma unroll
            for (int nf = 0; nf < 8; nf++) {
                int ncol = wn * 64 + nf * 8 + r0;
                b[nf][0] = *(const unsigned*)&Bs[cur][ncol][kb + 2*q    ];
                b[nf][1] = *(const unsigned*)&Bs[cur][ncol][kb + 2*q + 8];
            }
            #pragma unroll
            for (int mf = 0; mf < 2; mf++)
                #pragma unroll
                for (int nf = 0; nf < 8; nf++)
                    mma_f16(acc[mf][nf], a[mf][0], a[mf][1], a[mf][2], a[mf][3],
                            b[nf][0], b[nf][1]);
        }
        __syncthreads();
    }

    int hd = colBase / HID;
    float attSv[16], attDv[16];
    #pragma unroll
    for (int nf = 0; nf < 8; nf++) {
        int gc = colBase + wn * 64 + nf * 8 + 2 * q;
        attSv[nf*2]   = attS[gc];   attSv[nf*2+1] = attS[gc+1];
        attDv[nf*2]   = attD[gc];   attDv[nf*2+1] = attD[gc+1];
    }
    #pragma unroll
    for (int mf = 0; mf < 2; mf++) {
        int rT = wm * 32 + mf * 16 + r0;
        float psT = 0.f, pdT = 0.f, psB = 0.f, pdB = 0.f;
        #pragma unroll
        for (int nf = 0; nf < 8; nf++) {
            psT += acc[mf][nf][0]*attSv[nf*2] + acc[mf][nf][1]*attSv[nf*2+1];
            pdT += acc[mf][nf][0]*attDv[nf*2] + acc[mf][nf][1]*attDv[nf*2+1];
            psB += acc[mf][nf][2]*attSv[nf*2] + acc[mf][nf][3]*attSv[nf*2+1];
            pdB += acc[mf][nf][2]*attDv[nf*2] + acc[mf][nf][3]*attDv[nf*2+1];
        }
        #pragma unroll
        for (int o = 1; o < 4; o <<= 1) {
            psT += __shfl_xor_sync(0xffffffffu, psT, o);
            pdT += __shfl_xor_sync(0xffffffffu, pdT, o);
            psB += __shfl_xor_sync(0xffffffffu, psB, o);
            pdB += __shfl_xor_sync(0xffffffffu, pdB, o);
        }
        if (q == 0) {
            s_eas[wn][rT]     = psT;  s_ead[wn][rT]     = pdT;
            s_eas[wn][rT + 8] = psB;  s_ead[wn][rT + 8] = pdB;
        }
        #pragma unroll
        for (int nf = 0; nf < 8; nf++) {
            int gc = colBase + wn * 64 + nf * 8 + 2 * q;
            int gr0 = rowBase + rT;
            if (gr0 < M)
                *(__half2*)&Ch[(long long)gr0 * N + gc] =
                    __floats2half2_rn(acc[mf][nf][0], acc[mf][nf][1]);
            if (gr0 + 8 < M)
                *(__half2*)&Ch[(long long)(gr0 + 8) * N + gc] =
                    __floats2half2_rn(acc[mf][nf][2], acc[mf][nf][3]);
        }
    }
    __syncthreads();
    if (tid < GBM) {
        int gr = rowBase + tid;
        if (gr < M) {
            asOut[gr * heads + hd] = s_eas[0][tid] + s_eas[1][tid];
            adOut[gr * heads + hd] = s_ead[0][tid] + s_ead[1][tid];
        }
    }
}

__global__ __launch_bounds__(256) void gemm1_kernel(const float* __restrict__ as1,
                                                    const float* __restrict__ ad1) {
    f16_gemm_fused(g_xh, g_w1t, g_h1h, NN, F1, IN_CH, as1, ad1, g_as1, g_ad1,
                   HEADS, 0);
}

__global__ __launch_bounds__(256) void gemm2_kernel(const float* __restrict__ as2,
                                                    const float* __restrict__ ad2,
                                                    int rowBlockOff) {
    f16_gemm_fused(g_h1bh, g_w2t, g_h2h, NN, HID, F1, as2, ad2, g_as2, g_ad2,
                   1, rowBlockOff);
}

// ------------------------- layer-1 aggregation: single pass, vectorized ------
__global__ __launch_bounds__(128) void agg1_kernel(const float* __restrict__ b1,
                                                   int nodeOff) {
    int n = blockIdx.x + nodeOff, t = threadIdx.x;
    int beg = g_rowstart[n], end = g_rowstart[n + 1];
    int head = t >> 5;

    float4 adst = *(const float4*)&g_ad1[n * HEADS];

    __shared__ float4 s_w[32];
    __shared__ int    ssrc[32];
    __shared__ float  s_finv[HEADS];

    float acc0 = 0.f, acc1 = 0.f, acc2 = 0.f, acc3 = 0.f;
    float4 dsum = make_float4(0.f, 0.f, 0.f, 0.f);

    for (int base = beg; base < end; base += 32) {
        int cnt = min(32, end - base);
        __syncthreads();
        if (t < cnt) {
            int s = g_csrsrc[base + t];
            ssrc[t] = s;
            float4 a = *(const float4*)&g_as1[s * HEADS];
            float4 w;
            w.x = __expf(lrelu(a.x + adst.x));
            w.y = __expf(lrelu(a.y + adst.y));
            w.z = __expf(lrelu(a.z + adst.z));
            w.w = __expf(lrelu(a.w + adst.w));
            s_w[t] = w;
            dsum.x += w.x; dsum.y += w.y; dsum.z += w.z; dsum.w += w.w;
        }
        __syncthreads();
        for (int qq = 0; qq < cnt; qq++) {
            int s = ssrc[qq];
            float wq = ((const float*)&s_w[qq])[head];
            uint2 hv = *(const uint2*)&g_h1h[(long long)s * F1 + 4 * t];
            float2 f01 = __half22float2(*(__half2*)&hv.x);
            float2 f23 = __half22float2(*(__half2*)&hv.y);
            acc0 += wq * f01.x; acc1 += wq * f01.y;
            acc2 += wq * f23.x; acc3 += wq * f23.y;
        }
    }
    dsum.x = warpSum(dsum.x); dsum.y = warpSum(dsum.y);
    dsum.z = warpSum(dsum.z); dsum.w = warpSum(dsum.w);
    if (t == 0) {
        s_finv[0] = 1.f / dsum.x; s_finv[1] = 1.f / dsum.y;
        s_finv[2] = 1.f / dsum.z; s_finv[3] = 1.f / dsum.w;
    }
    __syncthreads();
    float fin = s_finv[head];
    float4 bv = *(const float4*)&b1[4 * t];
    __half2 h01 = __floats2half2_rn(fmaxf(acc0 * fin + bv.x, 0.f),
                                    fmaxf(acc1 * fin + bv.y, 0.f));
    __half2 h23 = __floats2half2_rn(fmaxf(acc2 * fin + bv.z, 0.f),
                                    fmaxf(acc3 * fin + bv.w, 0.f));
    *(uint2*)&g_h1bh[(long long)n * F1 + 4 * t] =
        make_uint2(*(unsigned*)&h01, *(unsigned*)&h23);
}

// ------------------------- layer-2 aggregation: single pass + fused pool ------
__global__ __launch_bounds__(128) void agg2_kernel(const float* __restrict__ b2,
                                                   const void* __restrict__ batch) {
    int n = blockIdx.x, t = threadIdx.x;
    int beg = g_rowstart[n], end = g_rowstart[n + 1];
    float adst = g_ad2[n];
    int grp = t >> 6;
    int c   = t & 63;

    __shared__ float s_w[64];
    __shared__ int   ssrc[64];
    __shared__ float s_accB[HID];
    __shared__ float wr2[2];

    float2 acc = make_float2(0.f, 0.f);
    float dsum = 0.f;

    for (int base = beg; base < end; base += 64) {
        int cnt = min(64, end - base);
        __syncthreads();
        if (t < cnt) {
            int s = g_csrsrc[base + t];
            ssrc[t] = s;
            float w = __expf(lrelu(g_as2[s] + adst));
            s_w[t] = w;
            dsum += w;
        }
        __syncthreads();
        for (int qq = grp; qq < cnt; qq += 2) {
            int s = ssrc[qq];
            float w = s_w[qq];
            float2 f = __half22float2(*(const __half2*)&g_h2h[(long long)s * HID + 2 * c]);
            acc.x += w * f.x; acc.y += w * f.y;
        }
    }
    dsum = warpSum(dsum);
    if ((t & 31) == 0 && t < 64) wr2[t >> 5] = dsum;
    if (grp == 1) { s_accB[2 * c] = acc.x; s_accB[2 * c + 1] = acc.y; }
    __syncthreads();
    if (grp == 0) {
        float di = 1.f / (wr2[0] + wr2[1]);
        float o0 = (acc.x + s_accB[2 * c])     * di + b2[2 * c];
        float o1 = (acc.y + s_accB[2 * c + 1]) * di + b2[2 * c + 1];
        int g = clampi(idx_at(batch, n), NG);
        atomicAdd(&g_pooled[g * HID + 2 * c],     o0);
        atomicAdd(&g_pooled[g * HID + 2 * c + 1], o1);
        if (t == 0) atomicAdd(&g_gcnt[g], 1.0f);
    }
}

// ------------------------- MLP head -------------------------
__global__ void mlp_kernel(const float* __restrict__ Wm1, const float* __restrict__ bm1,
                           const float* __restrict__ Wm2, const float* __restrict__ bm2,
                           float* __restrict__ out) {
    int g = blockIdx.x, t = threadIdx.x;
    __shared__ float p[HID], z[HID];
    float c = fmaxf(g_gcnt[g], 1.0f);
    p[t] = g_pooled[g * HID + t] / c;
    __syncthreads();
    float a = bm1[t];
    #pragma unroll 8
    for (int k = 0; k < HID; k++) a += p[k] * Wm1[k * HID + t];
    z[t] = a > 0.f ? a : 0.f;
    __syncthreads();
    if (t < OC) {
        float o = bm2[t];
        #pragma unroll 8
        for (int k = 0; k < HID; k++) o += z[k] * Wm2[k * OC + t];
        out[g * OC + t] = o;
    }
}

// ------------------------- launch -------------------------
// DAG:
//   s0: cvt_w2, CSR chain ............................ eCSR
//   s2: cvt_x, cvt_w1, gemm1 ......................... eGemm1
//   s0 (wait eGemm1):        agg1_lo -> gemm2_lo
//   s2 (wait eCSR):          agg1_hi -> gemm2_hi ..... eG2hi
//   s0 (wait eG2hi):         agg2 -> mlp
// gemm2 row-block b reads only h1b rows in that block, so per-half ordering
// on each stream is sufficient; agg2 gathers arbitrary h2 rows so it joins both.
// Streams/events created fresh per call, never destroyed (graph-capture safe).
extern "C" void kernel_launch(void* const* d_in, const int* in_sizes, int n_in,
                              void* d_out, int out_size) {
    const float* x    = (const float*)d_in[0];
    const void*  ei   = d_in[1];
    const void*  bat  = d_in[2];
    const float* W1   = (const float*)d_in[3];
    const float* as1  = (const float*)d_in[4];
    const float* ad1  = (const float*)d_in[5];
    const float* b1   = (const float*)d_in[6];
    const float* W2   = (const float*)d_in[7];
    const float* as2  = (const float*)d_in[8];
    const float* ad2  = (const float*)d_in[9];
    const float* b2   = (const float*)d_in[10];
    const float* Wm1  = (const float*)d_in[11];
    const float* bm1  = (const float*)d_in[12];
    const float* Wm2  = (const float*)d_in[13];
    const float* bm2  = (const float*)d_in[14];
    float* out = (float*)d_out;

    cudaStream_t s2;
    cudaStreamCreateWithFlags(&s2, cudaStreamNonBlocking);
    cudaEvent_t eFork, eGemm1, eCSR, eG2hi;
    cudaEventCreateWithFlags(&eFork,  cudaEventDisableTiming);
    cudaEventCreateWithFlags(&eGemm1, cudaEventDisableTiming);
    cudaEventCreateWithFlags(&eCSR,   cudaEventDisableTiming);
    cudaEventCreateWithFlags(&eG2hi,  cudaEventDisableTiming);

    // fork
    cudaEventRecord(eFork, 0);
    cudaStreamWaitEvent(s2, eFork, 0);

    // s2: fp16 conversions + gemm1
    cvt_x_kernel <<<(NN * IN_CH / 4 + 255) / 256, 256, 0, s2>>>(x);
    cvt_w1_kernel<<<(F1 * IN_CH + 255) / 256, 256, 0, s2>>>(W1);
    {
        dim3 grid(F1 / GBN, RB_ALL);
        gemm1_kernel<<<grid, 256, 0, s2>>>(as1, ad1);
    }
    cudaEventRecord(eGemm1, s2);

    // s0: W2 convert + CSR build
    cvt_w2_kernel<<<(HID * F1 + 255) / 256, 256>>>(W2);
    zero_kernel<<<(NN + 255) / 256, 256>>>((const int*)ei);   // must cover NN!
    hist_kernel<<<(NET + 255) / 256, 256>>>(ei);
    scan1_kernel<<<SNB, SCH>>>();
    scan3_kernel<<<(NN + 255) / 256, 256>>>();
    scatter_kernel<<<(NET + 255) / 256, 256>>>(ei);
    cudaEventRecord(eCSR, 0);

    // s0: lo half — agg1 then gemm2 (needs gemm1 output + CSR)
    cudaStreamWaitEvent(0, eGemm1, 0);
    agg1_kernel<<<NLO, 128>>>(b1, 0);
    {
        dim3 grid(HID / GBN, RB_LO);
        gemm2_kernel<<<grid, 256>>>(as2, ad2, 0);
    }

    // s2: hi half — agg1 then gemm2 (gemm1 already on s2; wait CSR)
    cudaStreamWaitEvent(s2, eCSR, 0);
    agg1_kernel<<<NN - NLO, 128, 0, s2>>>(b1, NLO);
    {
        dim3 grid(HID / GBN, RB_HI);
        gemm2_kernel<<<grid, 256, 0, s2>>>(as2, ad2, RB_LO);
    }
    cudaEventRecord(eG2hi, s2);

    // join: agg2 needs full g_h2h + g_as2/g_ad2
    cudaStreamWaitEvent(0, eG2hi, 0);
    agg2_kernel<<<NN, 128>>>(b2, bat);

    mlp_kernel<<<NG, HID>>>(Wm1, bm1, Wm2, bm2, out);
}